// round 11
// baseline (speedup 1.0000x reference)
#include <cuda_runtime.h>
#include <math.h>
#include <stdint.h>

// Problem constants
#define TSEQ 2048
#define NHEAD 16
#define HDIM 128
// mask: keep k < 204 or k >= 1229 ; evict = 1229 ; recent rb = 819
// last_start = 1792 ; mean over k in [1230, 2048) -> 818 elements

// ---------------- scratch (static device globals; no allocation) -------------
__device__ float g_q[NHEAD * TSEQ * HDIM];   // [h][t][d], rope applied
__device__ float g_k[NHEAD * TSEQ * HDIM];
__device__ float g_v[NHEAD * TSEQ * HDIM];
__device__ float g_ctx[TSEQ * 2048];         // [t][h*128+d]
__device__ float g_ve[NHEAD * HDIM];         // v_e per head (includes bern/rb)

// nan_to_num(nan=0, posinf=1e4, neginf=-1e4): replaces non-finite ONLY
__device__ __forceinline__ float nn_fix(float x) {
    if (isnan(x)) return 0.0f;
    if (isinf(x)) return x > 0.0f ? 10000.0f : -10000.0f;
    return x;
}

__device__ __forceinline__ float tf32rna(float x) {
    float r;
    asm("cvt.rna.tf32.f32 %0, %1;" : "=f"(r) : "f"(x));
    return r;
}

// portable (non-'a') tensor core: mma.sync m16n8k8 tf32, fp32 accumulate
__device__ __forceinline__ void mma_tf32(float* d, const uint32_t* a,
                                         const uint32_t* b) {
    asm volatile(
        "mma.sync.aligned.m16n8k8.row.col.f32.tf32.tf32.f32 "
        "{%0,%1,%2,%3}, {%4,%5,%6,%7}, {%8,%9}, {%0,%1,%2,%3};"
        : "+f"(d[0]), "+f"(d[1]), "+f"(d[2]), "+f"(d[3])
        : "r"(a[0]), "r"(a[1]), "r"(a[2]), "r"(a[3]), "r"(b[0]), "r"(b[1]));
}

// ============ mma.sync TF32x3 GEMM: C[M,N] = A[M,K] * B[N,K]^T ===============
// M=N=K=2048, CTA tile 128x128, 256 threads (8 warps, 2x4), warp tile 64x32.
// SMEM holds fp32 tiles (hi/lo split done in REGISTERS after fragment load).
// Double-buffered stages; ONE __syncthreads per chunk.
// Term loop OUTERMOST within each k-step: 16 independent accumulators between
// reuses of the same accumulator (breaks the HMMA RAW chain).
// Row stride 36 -> fragment LDS.32 bank = (4g + tig) mod 32, conflict-free.
#define G_LDS 36
#define G_TILE_FLOATS (128 * G_LDS)
#define G_SMEM_FLOATS (4 * G_TILE_FLOATS)   // 2 stages x (A, B)
#define G_SMEM_BYTES  (G_SMEM_FLOATS * 4)

__global__ void __launch_bounds__(256, 1)
gemm_tc_kernel(const float* __restrict__ Aext, const float* __restrict__ B,
               float* __restrict__ Cext, int mode)
{
    extern __shared__ float gsm[];
    const float* Aglob = (mode == 3) ? (const float*)g_ctx : Aext;
    const bool fixA = (mode != 3);

    const int tid  = threadIdx.x;
    const int wid  = tid >> 5;
    const int lane = tid & 31;
    const int g    = lane >> 2;     // fragment row 0..7
    const int tig  = lane & 3;      // fragment col 0..3
    const int bm = blockIdx.y, bn = blockIdx.x;

    const int warp_m = (wid >> 2) * 64;   // 0 or 64
    const int warp_n = (wid & 3) * 32;    // 0,32,64,96

    float c[4][4][4];
#pragma unroll
    for (int i = 0; i < 4; ++i)
#pragma unroll
        for (int j = 0; j < 4; ++j)
#pragma unroll
            for (int q = 0; q < 4; ++q) c[i][j][q] = 0.0f;

    const float* Ab = Aglob + (size_t)(bm * 128) * 2048;
    const float* Bb = B + (size_t)(bn * 128) * 2048;

    // GMEM load assignment: row = tid>>1, k-half = (tid&1)*16
    const int gr = tid >> 1;
    const int gk = (tid & 1) * 16;
    const int sbase = gr * G_LDS + gk;

    float4 apf[4], bpf[4];
    // ---- chunk 0: prefetch + store to stage 0 ----
#pragma unroll
    for (int i = 0; i < 4; ++i) {
        apf[i] = *(const float4*)(Ab + (size_t)gr * 2048 + gk + i * 4);
        bpf[i] = *(const float4*)(Bb + (size_t)gr * 2048 + gk + i * 4);
    }
#pragma unroll
    for (int i = 0; i < 4; ++i) {
        float4 va = apf[i];
        if (fixA) {
            va.x = nn_fix(va.x); va.y = nn_fix(va.y);
            va.z = nn_fix(va.z); va.w = nn_fix(va.w);
        }
        *(float4*)&gsm[sbase + 4 * i] = va;
        *(float4*)&gsm[G_TILE_FLOATS + sbase + 4 * i] = bpf[i];
    }

    for (int ch = 0; ch < 64; ++ch) {
        const int s = ch & 1;
        float* As = gsm + (size_t)s * (2 * G_TILE_FLOATS);
        float* Bs = As + G_TILE_FLOATS;
        __syncthreads();    // stage s stores visible; stage s^1 fully consumed

        // prefetch next chunk (overlaps compute below)
        if (ch < 63) {
            const int k0n = (ch + 1) * 32;
#pragma unroll
            for (int i = 0; i < 4; ++i) {
                apf[i] = *(const float4*)(Ab + (size_t)gr * 2048 + k0n + gk + i * 4);
                bpf[i] = *(const float4*)(Bb + (size_t)gr * 2048 + k0n + gk + i * 4);
            }
        }

        // ---- compute: 4 k-steps; fp32 fragment load, register hi/lo split ----
#pragma unroll
        for (int ks = 0; ks < 4; ++ks) {
            const int off = ks * 8 + tig;
            float ar[4][4], br[4][2];
#pragma unroll
            for (int mt = 0; mt < 4; ++mt) {
                const int r0 = (warp_m + mt * 16 + g) * G_LDS + off;
                ar[mt][0] = As[r0];
                ar[mt][1] = As[r0 + 8 * G_LDS];
                ar[mt][2] = As[r0 + 4];
                ar[mt][3] = As[r0 + 8 * G_LDS + 4];
            }
#pragma unroll
            for (int nt = 0; nt < 4; ++nt) {
                const int n0 = (warp_n + nt * 8 + g) * G_LDS + off;
                br[nt][0] = Bs[n0];
                br[nt][1] = Bs[n0 + 4];
            }
            uint32_t ahf[4][4], alf[4][4], bhf[4][2], blf[4][2];
#pragma unroll
            for (int mt = 0; mt < 4; ++mt)
#pragma unroll
                for (int q = 0; q < 4; ++q) {
                    const float h = tf32rna(ar[mt][q]);
                    ahf[mt][q] = __float_as_uint(h);
                    alf[mt][q] = __float_as_uint(tf32rna(ar[mt][q] - h));
                }
#pragma unroll
            for (int nt = 0; nt < 4; ++nt)
#pragma unroll
                for (int q = 0; q < 2; ++q) {
                    const float h = tf32rna(br[nt][q]);
                    bhf[nt][q] = __float_as_uint(h);
                    blf[nt][q] = __float_as_uint(tf32rna(br[nt][q] - h));
                }
            // term-outer ordering: per accumulator the update order is still
            // (Ah*Bh, Ah*Bl, Al*Bh) within this ks -> BIT-IDENTICAL result,
            // but consecutive MMAs now touch 16 independent accumulators.
#pragma unroll
            for (int mt = 0; mt < 4; ++mt)
#pragma unroll
                for (int nt = 0; nt < 4; ++nt)
                    mma_tf32(c[mt][nt], ahf[mt], bhf[nt]);
#pragma unroll
            for (int mt = 0; mt < 4; ++mt)
#pragma unroll
                for (int nt = 0; nt < 4; ++nt)
                    mma_tf32(c[mt][nt], ahf[mt], blf[nt]);
#pragma unroll
            for (int mt = 0; mt < 4; ++mt)
#pragma unroll
                for (int nt = 0; nt < 4; ++nt)
                    mma_tf32(c[mt][nt], alf[mt], bhf[nt]);
        }

        // ---- store prefetched chunk into the other stage (consumed pre-sync) ----
        if (ch < 63) {
            float* An = gsm + (size_t)(s ^ 1) * (2 * G_TILE_FLOATS);
            float* Bn = An + G_TILE_FLOATS;
#pragma unroll
            for (int i = 0; i < 4; ++i) {
                float4 va = apf[i];
                if (fixA) {
                    va.x = nn_fix(va.x); va.y = nn_fix(va.y);
                    va.z = nn_fix(va.z); va.w = nn_fix(va.w);
                }
                *(float4*)&An[sbase + 4 * i] = va;
                *(float4*)&Bn[sbase + 4 * i] = bpf[i];
            }
        }
    }

    // ---- epilogue ----
#pragma unroll
    for (int mt = 0; mt < 4; ++mt) {
        const int row0 = bm * 128 + warp_m + mt * 16 + g;
#pragma unroll
        for (int nt = 0; nt < 4; ++nt) {
            const int coln = warp_n + nt * 8 + 2 * tig;
            if (mode == 3) {
                float* d0 = Cext + (size_t)row0 * 2048 + bn * 128 + coln;
                float* d1 = Cext + (size_t)(row0 + 8) * 2048 + bn * 128 + coln;
                d0[0] = nn_fix(c[mt][nt][0]); d0[1] = nn_fix(c[mt][nt][1]);
                d1[0] = nn_fix(c[mt][nt][2]); d1[1] = nn_fix(c[mt][nt][3]);
            } else {
                float* Cg = (mode == 0) ? g_q : (mode == 1) ? g_k : g_v;
                float* base = Cg + (size_t)bn * (TSEQ * HDIM);
                *(float2*)&base[(size_t)row0 * HDIM + coln] =
                    make_float2(c[mt][nt][0], c[mt][nt][1]);
                *(float2*)&base[(size_t)(row0 + 8) * HDIM + coln] =
                    make_float2(c[mt][nt][2], c[mt][nt][3]);
            }
        }
    }
}

// ---------------- RoPE in-place on g_q, g_k ----------------------------------
__global__ void rope_kernel()
{
    const int t = blockIdx.x;      // 0..2047
    const int i = threadIdx.x;     // 0..63 (pair index)
    const float pw = (float)pow(10000.0, (double)(2 * i) / 128.0);
    const float inv = 1.0f / pw;
    const float freq = (float)t * inv;
    const float c = cosf(freq);
    const float s = sinf(freq);
#pragma unroll 4
    for (int h = 0; h < NHEAD; ++h) {
        float* q = g_q + ((size_t)(h * TSEQ + t)) * HDIM;
        float x1 = q[i], x2 = q[i + 64];
        q[i]      = __fadd_rn(__fmul_rn(x1, c), __fmul_rn(-x2, s));
        q[i + 64] = __fadd_rn(__fmul_rn(x2, c), __fmul_rn(x1, s));
        float* k = g_k + ((size_t)(h * TSEQ + t)) * HDIM;
        float y1 = k[i], y2 = k[i + 64];
        k[i]      = __fadd_rn(__fmul_rn(y1, c), __fmul_rn(-y2, s));
        k[i + 64] = __fadd_rn(__fmul_rn(y2, c), __fmul_rn(y1, s));
    }
}

// ---------------- threefry-2x32, PARTITIONABLE path --------------------------
__device__ __forceinline__ unsigned rotl32(unsigned x, int d) {
    return (x << d) | (x >> (32 - d));
}

__device__ float jax_uniform42_partitionable(int h)
{
    const unsigned k0 = 0u, k1 = 42u;
    const unsigned k2 = k0 ^ k1 ^ 0x1BD11BDAu;
    const unsigned ks[3] = { k0, k1, k2 };
    unsigned x0 = 0u + k0;              // counter hi = 0
    unsigned x1 = (unsigned)h + k1;     // counter lo = h
    const int rotA[4] = { 13, 15, 26, 6 };
    const int rotB[4] = { 17, 29, 16, 24 };
#pragma unroll
    for (int i = 0; i < 5; ++i) {
        const int* R = (i & 1) ? rotB : rotA;
#pragma unroll
        for (int j = 0; j < 4; ++j) {
            x0 += x1;
            x1 = rotl32(x1, R[j]);
            x1 ^= x0;
        }
        x0 += ks[(i + 1) % 3];
        x1 += ks[(i + 2) % 3] + (unsigned)(i + 1);
    }
    const unsigned bits = x0 ^ x1;
    return __uint_as_float((bits >> 9) | 0x3f800000u) - 1.0f;
}

// ---------------- last-row stats: p, bern, v_e per head ----------------------
__global__ void __launch_bounds__(256) lastrow_kernel()
{
    const int h = blockIdx.x;
    const int tid = threadIdx.x;
    __shared__ float qv[128];
    __shared__ float s[2048];
    __shared__ float red[256];
    __shared__ float red2[256];
    __shared__ float sh_scale;

    if (tid < 128) qv[tid] = g_q[((size_t)h * TSEQ + 2047) * HDIM + tid];
    __syncthreads();

    for (int k = tid; k < 2048; k += 256) {
        const bool keep = (k < 204) || (k >= 1229);
        float val = -INFINITY;
        if (keep) {
            const float4* kr = (const float4*)(g_k + ((size_t)h * TSEQ + k) * HDIM);
            const float4* q4 = (const float4*)qv;
            float dot = 0.0f;
#pragma unroll
            for (int d4 = 0; d4 < 32; ++d4) {
                float4 a = q4[d4]; float4 b = kr[d4];
                dot = fmaf(a.x, b.x, dot); dot = fmaf(a.y, b.y, dot);
                dot = fmaf(a.z, b.z, dot); dot = fmaf(a.w, b.w, dot);
            }
            val = dot / 11.313708498984760f;  // / sqrt(128)
        }
        s[k] = val;
    }
    __syncthreads();

    float lm = -INFINITY;
    for (int k = tid; k < 2048; k += 256) lm = fmaxf(lm, s[k]);
    red[tid] = lm;
    __syncthreads();
    for (int st = 128; st > 0; st >>= 1) {
        if (tid < st) red[tid] = fmaxf(red[tid], red[tid + st]);
        __syncthreads();
    }
    const float m = red[0];
    __syncthreads();

    float ls = 0.0f, lrS = 0.0f;
    for (int k = tid; k < 2048; k += 256) {
        if ((k < 204) || (k >= 1229)) {
            const float e = expf(s[k] - m);
            ls += e;
            if (k >= 1230) lrS += e;
        }
    }
    red[tid] = ls; red2[tid] = lrS;
    __syncthreads();
    for (int st = 128; st > 0; st >>= 1) {
        if (tid < st) { red[tid] += red[tid + st]; red2[tid] += red2[tid + st]; }
        __syncthreads();
    }
    if (tid == 0) {
        const float L = red[0], R = red2[0];
        const float Pev = expf(s[1229] - m) / L;
        const float mean = (R / L) / 818.0f + 1e-6f;
        float p = Pev / mean;
        if (isnan(p)) p = 0.0f;
        p = fminf(fmaxf(p, 0.0f), 1.0f);
        const float u = jax_uniform42_partitionable(h);
        sh_scale = (u < p) ? 1.0f : 0.0f;
    }
    __syncthreads();
    if (tid < 128)
        g_ve[h * HDIM + tid] =
            (g_v[((size_t)h * TSEQ + 1229) * HDIM + tid] * sh_scale) / 819.0f;
}

// ---------------- flash-style attention over kept K columns ------------------
// (R5 scalar version — proven fastest FFMA formulation)
#define ATTN_SMEM_FLOATS (64*129 + 64*129 + 64*132 + 64*66 + 256)
#define ATTN_SMEM_BYTES  (ATTN_SMEM_FLOATS * 4)

__global__ void __launch_bounds__(256) attn_kernel()
{
    extern __shared__ float sm[];
    float* Qs   = sm;
    float* Ks   = Qs + 64 * 129;
    float* Vs   = Ks + 64 * 129;
    float* S    = Vs + 64 * 132;
    float* m_s  = S + 64 * 66;
    float* l_s  = m_s + 64;
    float* lr_s = l_s + 64;
    float* fac_s = lr_s + 64;

    const int h   = blockIdx.y;
    const int qt  = blockIdx.x;
    const int tid = threadIdx.x;
    const int ty  = tid >> 4;
    const int tx  = tid & 15;
    const int r0  = ty << 2;
    const int cS0 = tx << 2;
    const int cV0 = tx << 3;

    const int ldr = tid >> 5;
    const int ldc = (tid & 31) << 2;

    const float* qbase = g_q + ((size_t)h * TSEQ + qt * 64) * HDIM;
#pragma unroll
    for (int it = 0; it < 8; ++it) {
        const int j = ldr + it * 8;
        float4 v = *(const float4*)(qbase + (size_t)j * HDIM + ldc);
        Qs[j * 129 + ldc + 0] = v.x; Qs[j * 129 + ldc + 1] = v.y;
        Qs[j * 129 + ldc + 2] = v.z; Qs[j * 129 + ldc + 3] = v.w;
    }
    if (tid < 64) { m_s[tid] = -INFINITY; l_s[tid] = 0.0f; lr_s[tid] = 0.0f; }

    float acc[4][8];
#pragma unroll
    for (int i = 0; i < 4; ++i)
#pragma unroll
        for (int j = 0; j < 8; ++j) acc[i][j] = 0.0f;

    __syncthreads();

    for (int tile = 0; tile < 17; ++tile) {
        const int kb   = (tile < 4) ? tile * 64 : 1229 + (tile - 4) * 64;
        const int kend = (tile < 4) ? 204 : 2048;

#pragma unroll
        for (int it = 0; it < 8; ++it) {
            const int j = ldr + it * 8;
            const int kc = kb + j;
            float4 kv = make_float4(0.f, 0.f, 0.f, 0.f);
            float4 vv = kv;
            if (kc < kend) {
                kv = *(const float4*)(g_k + ((size_t)h * TSEQ + kc) * HDIM + ldc);
                vv = *(const float4*)(g_v + ((size_t)h * TSEQ + kc) * HDIM + ldc);
            }
            Ks[j * 129 + ldc + 0] = kv.x; Ks[j * 129 + ldc + 1] = kv.y;
            Ks[j * 129 + ldc + 2] = kv.z; Ks[j * 129 + ldc + 3] = kv.w;
            *(float4*)&Vs[j * 132 + ldc] = vv;
        }
        __syncthreads();

        float sacc[4][4];
#pragma unroll
        for (int i = 0; i < 4; ++i)
#pragma unroll
            for (int j = 0; j < 4; ++j) sacc[i][j] = 0.0f;

        const float* q0 = Qs + (r0 + 0) * 129;
        const float* q1 = Qs + (r0 + 1) * 129;
        const float* q2 = Qs + (r0 + 2) * 129;
        const float* q3 = Qs + (r0 + 3) * 129;
        const float* kp0 = Ks + (cS0 + 0) * 129;
        const float* kp1 = Ks + (cS0 + 1) * 129;
        const float* kp2 = Ks + (cS0 + 2) * 129;
        const float* kp3 = Ks + (cS0 + 3) * 129;
#pragma unroll 8
        for (int kk = 0; kk < 128; ++kk) {
            const float a0 = q0[kk], a1 = q1[kk], a2 = q2[kk], a3 = q3[kk];
            const float b0 = kp0[kk], b1 = kp1[kk], b2 = kp2[kk], b3 = kp3[kk];
            sacc[0][0] = fmaf(a0, b0, sacc[0][0]); sacc[0][1] = fmaf(a0, b1, sacc[0][1]);
            sacc[0][2] = fmaf(a0, b2, sacc[0][2]); sacc[0][3] = fmaf(a0, b3, sacc[0][3]);
            sacc[1][0] = fmaf(a1, b0, sacc[1][0]); sacc[1][1] = fmaf(a1, b1, sacc[1][1]);
            sacc[1][2] = fmaf(a1, b2, sacc[1][2]); sacc[1][3] = fmaf(a1, b3, sacc[1][3]);
            sacc[2][0] = fmaf(a2, b0, sacc[2][0]); sacc[2][1] = fmaf(a2, b1, sacc[2][1]);
            sacc[2][2] = fmaf(a2, b2, sacc[2][2]); sacc[2][3] = fmaf(a2, b3, sacc[2][3]);
            sacc[3][0] = fmaf(a3, b0, sacc[3][0]); sacc[3][1] = fmaf(a3, b1, sacc[3][1]);
            sacc[3][2] = fmaf(a3, b2, sacc[3][2]); sacc[3][3] = fmaf(a3, b3, sacc[3][3]);
        }
#pragma unroll
        for (int i = 0; i < 4; ++i)
#pragma unroll
            for (int j = 0; j < 4; ++j) {
                const int kc = kb + cS0 + j;
                S[(r0 + i) * 66 + cS0 + j] =
                    (kc < kend) ? sacc[i][j] / 11.313708498984760f : -1e30f;
            }
        __syncthreads();

        if (tid < 64) {
            const int r = tid;
            float* Sr = S + r * 66;
            float tm = -1e30f;
#pragma unroll 8
            for (int j = 0; j < 64; ++j) tm = fmaxf(tm, Sr[j]);
            const float mo = m_s[r];
            const float mn = fmaxf(mo, tm);
            const float fac = expf(mo - mn);
            float sum = 0.0f, sumr = 0.0f;
#pragma unroll 4
            for (int j = 0; j < 64; ++j) {
                const float e = expf(Sr[j] - mn);
                Sr[j] = e;
                sum += e;
                if (kb + j >= 1230) sumr += e;
            }
            l_s[r]  = l_s[r]  * fac + sum;
            lr_s[r] = lr_s[r] * fac + sumr;
            m_s[r]  = mn;
            fac_s[r] = fac;
        }
        __syncthreads();

        {
            const float f0 = fac_s[r0 + 0], f1 = fac_s[r0 + 1];
            const float f2 = fac_s[r0 + 2], f3 = fac_s[r0 + 3];
#pragma unroll
            for (int j = 0; j < 8; ++j) {
                acc[0][j] *= f0; acc[1][j] *= f1; acc[2][j] *= f2; acc[3][j] *= f3;
            }
        }
#pragma unroll 2
        for (int jp = 0; jp < 64; ++jp) {
            const float p0 = S[(r0 + 0) * 66 + jp];
            const float p1 = S[(r0 + 1) * 66 + jp];
            const float p2 = S[(r0 + 2) * 66 + jp];
            const float p3 = S[(r0 + 3) * 66 + jp];
            float vv[8];
            *(float4*)&vv[0] = *(const float4*)&Vs[jp * 132 + cV0];
            *(float4*)&vv[4] = *(const float4*)&Vs[jp * 132 + cV0 + 4];
#pragma unroll
            for (int j = 0; j < 8; ++j) {
                acc[0][j] = fmaf(p0, vv[j], acc[0][j]);
                acc[1][j] = fmaf(p1, vv[j], acc[1][j]);
                acc[2][j] = fmaf(p2, vv[j], acc[2][j]);
                acc[3][j] = fmaf(p3, vv[j], acc[3][j]);
            }
        }
        __syncthreads();
    }

    const int qg0 = qt * 64;
#pragma unroll
    for (int i = 0; i < 4; ++i) {
        const int r = r0 + i;
        const int qrow = qg0 + r;
        const float linv = 1.0f / l_s[r];
        const float corr = (qrow >= 1792) ? lr_s[r] * linv : 0.0f;
#pragma unroll
        for (int j = 0; j < 8; ++j) {
            const int dcol = cV0 + j;
            const float o = acc[i][j] * linv + corr * g_ve[h * HDIM + dcol];
            g_ctx[(size_t)qrow * 2048 + h * HDIM + dcol] = o;
        }
    }
}

// ---------------- launch ------------------------------------------------------
extern "C" void kernel_launch(void* const* d_in, const int* in_sizes, int n_in,
                              void* d_out, int out_size)
{
    (void)in_sizes; (void)n_in; (void)out_size;
    const float* hs = (const float*)d_in[0];
    const float* Wq = (const float*)d_in[1];
    const float* Wk = (const float*)d_in[2];
    const float* Wv = (const float*)d_in[3];
    const float* Wo = (const float*)d_in[4];
    float* out = (float*)d_out;

    cudaFuncSetAttribute(gemm_tc_kernel,
                         cudaFuncAttributeMaxDynamicSharedMemorySize,
                         G_SMEM_BYTES);
    cudaFuncSetAttribute(attn_kernel,
                         cudaFuncAttributeMaxDynamicSharedMemorySize,
                         ATTN_SMEM_BYTES);

    dim3 ggrid(16, 16);
    gemm_tc_kernel<<<ggrid, 256, G_SMEM_BYTES>>>(hs, Wq, nullptr, 0);
    gemm_tc_kernel<<<ggrid, 256, G_SMEM_BYTES>>>(hs, Wk, nullptr, 1);
    gemm_tc_kernel<<<ggrid, 256, G_SMEM_BYTES>>>(hs, Wv, nullptr, 2);
    rope_kernel<<<2048, 64>>>();
    lastrow_kernel<<<16, 256>>>();
    attn_kernel<<<dim3(32, 16), 256, ATTN_SMEM_BYTES>>>();
    gemm_tc_kernel<<<ggrid, 256, G_SMEM_BYTES>>>(nullptr, Wo, out, 3);
}

// round 12
// speedup vs baseline: 1.2031x; 1.2031x over previous
#include <cuda_runtime.h>
#include <cuda_bf16.h>
#include <math.h>
#include <stdint.h>

// Problem constants
#define TSEQ 2048
#define NHEAD 16
#define HDIM 128
// mask: keep k < 204 or k >= 1229 ; evict = 1229 ; recent rb = 819
// last_start = 1792 ; mean over k in [1230, 2048) -> 818 elements

// ---------------- scratch (static device globals; no allocation) -------------
__device__ float g_q[NHEAD * TSEQ * HDIM];   // [h][t][d], rope applied
__device__ float g_k[NHEAD * TSEQ * HDIM];
__device__ float g_v[NHEAD * TSEQ * HDIM];
__device__ float g_ctx[TSEQ * 2048];         // [t][h*128+d]
__device__ float g_ve[NHEAD * HDIM];         // v_e per head (includes bern/rb)

// nan_to_num(nan=0, posinf=1e4, neginf=-1e4): replaces non-finite ONLY
__device__ __forceinline__ float nn_fix(float x) {
    if (isnan(x)) return 0.0f;
    if (isinf(x)) return x > 0.0f ? 10000.0f : -10000.0f;
    return x;
}

// pack two floats to bf16x2 word (lo in bits[0:16), hi in bits[16:32))
__device__ __forceinline__ uint32_t bf2(float lo, float hi) {
    uint32_t r;
    asm("cvt.rn.bf16x2.f32 %0, %1, %2;" : "=r"(r) : "f"(hi), "f"(lo));
    return r;
}

// bf16x3 split of a float4 (k-pairs (x,y) and (z,w)) -> hi uint2, lo uint2
__device__ __forceinline__ void split4(float4 v, uint2& hw, uint2& lw) {
    const uint32_t h0 = bf2(v.x, v.y);
    const float f0 = __uint_as_float(h0 << 16);
    const float f1 = __uint_as_float(h0 & 0xffff0000u);
    const uint32_t l0 = bf2(v.x - f0, v.y - f1);
    const uint32_t h1 = bf2(v.z, v.w);
    const float f2 = __uint_as_float(h1 << 16);
    const float f3 = __uint_as_float(h1 & 0xffff0000u);
    const uint32_t l1 = bf2(v.z - f2, v.w - f3);
    hw = make_uint2(h0, h1);
    lw = make_uint2(l0, l1);
}

// portable tensor core: mma.sync m16n8k16 bf16, fp32 accumulate
__device__ __forceinline__ void mma_bf16(float* d, const uint32_t* a,
                                         const uint32_t* b) {
    asm volatile(
        "mma.sync.aligned.m16n8k16.row.col.f32.bf16.bf16.f32 "
        "{%0,%1,%2,%3}, {%4,%5,%6,%7}, {%8,%9}, {%0,%1,%2,%3};"
        : "+f"(d[0]), "+f"(d[1]), "+f"(d[2]), "+f"(d[3])
        : "r"(a[0]), "r"(a[1]), "r"(a[2]), "r"(a[3]), "r"(b[0]), "r"(b[1]));
}

// ============ mma.sync BF16x3 GEMM: C[M,N] = A[M,K] * B[N,K]^T ===============
// M=N=K=2048, CTA tile 128x128, 256 threads (8 warps, 2x4), warp tile 64x32.
// SMEM: bf16-packed hi/lo tiles (u32 words = k-pairs). 16 words/row/chunk,
// row stride 20 words -> fragment LDS.32 bank = (20g+tig) mod 32, bijective
// over the warp -> conflict-free. Double buffered, one sync per chunk.
// k16 per MMA -> HALF the HMMA count of the tf32(k8) version.
#define GW_LDS 20
#define GW_TILE (128 * GW_LDS)               // u32 per tile
#define G_SMEM_BYTES (2 * 4 * GW_TILE * 4)   // 2 stages x (Ah,Al,Bh,Bl)

__global__ void __launch_bounds__(256, 1)
gemm_tc_kernel(const float* __restrict__ Aext, const float* __restrict__ B,
               float* __restrict__ Cext, int mode)
{
    extern __shared__ uint32_t gsm32[];
    const float* Aglob = (mode == 3) ? (const float*)g_ctx : Aext;
    const bool fixA = (mode != 3);

    const int tid  = threadIdx.x;
    const int wid  = tid >> 5;
    const int lane = tid & 31;
    const int g    = lane >> 2;     // fragment row 0..7
    const int tig  = lane & 3;      // fragment col 0..3
    const int bm = blockIdx.y, bn = blockIdx.x;

    const int warp_m = (wid >> 2) * 64;   // 0 or 64
    const int warp_n = (wid & 3) * 32;    // 0,32,64,96

    float c[4][4][4];
#pragma unroll
    for (int i = 0; i < 4; ++i)
#pragma unroll
        for (int j = 0; j < 4; ++j)
#pragma unroll
            for (int q = 0; q < 4; ++q) c[i][j][q] = 0.0f;

    const float* Ab = Aglob + (size_t)(bm * 128) * 2048;
    const float* Bb = B + (size_t)(bn * 128) * 2048;

    // GMEM load assignment: row = tid>>1, k-half = (tid&1)*16 floats
    const int gr = tid >> 1;
    const int gk = (tid & 1) * 16;
    const int wbase = gr * GW_LDS + (gk >> 1);   // word base in row

    float4 apf[4], bpf[4];
#pragma unroll
    for (int i = 0; i < 4; ++i) {
        apf[i] = *(const float4*)(Ab + (size_t)gr * 2048 + gk + i * 4);
        bpf[i] = *(const float4*)(Bb + (size_t)gr * 2048 + gk + i * 4);
    }
    // ---- chunk 0: split + store to stage 0 ----
    {
        uint32_t* AhS = gsm32;
        uint32_t* AlS = AhS + GW_TILE;
        uint32_t* BhS = AlS + GW_TILE;
        uint32_t* BlS = BhS + GW_TILE;
#pragma unroll
        for (int i = 0; i < 4; ++i) {
            float4 va = apf[i];
            if (fixA) {
                va.x = nn_fix(va.x); va.y = nn_fix(va.y);
                va.z = nn_fix(va.z); va.w = nn_fix(va.w);
            }
            uint2 hw, lw;
            split4(va, hw, lw);
            *(uint2*)&AhS[wbase + 2 * i] = hw;
            *(uint2*)&AlS[wbase + 2 * i] = lw;
            split4(bpf[i], hw, lw);
            *(uint2*)&BhS[wbase + 2 * i] = hw;
            *(uint2*)&BlS[wbase + 2 * i] = lw;
        }
    }

    for (int ch = 0; ch < 64; ++ch) {
        const int s = ch & 1;
        uint32_t* AhS = gsm32 + (size_t)s * (4 * GW_TILE);
        uint32_t* AlS = AhS + GW_TILE;
        uint32_t* BhS = AlS + GW_TILE;
        uint32_t* BlS = BhS + GW_TILE;
        __syncthreads();    // stage s visible; stage s^1 fully consumed

        // prefetch next chunk (overlaps compute below)
        if (ch < 63) {
            const int k0n = (ch + 1) * 32;
#pragma unroll
            for (int i = 0; i < 4; ++i) {
                apf[i] = *(const float4*)(Ab + (size_t)gr * 2048 + k0n + gk + i * 4);
                bpf[i] = *(const float4*)(Bb + (size_t)gr * 2048 + k0n + gk + i * 4);
            }
        }

        // ---- compute: 2 k16-steps, 3 bf16 terms each ----
#pragma unroll
        for (int ks = 0; ks < 2; ++ks) {
            const int off = ks * 8 + tig;
            uint32_t ah[4][4], al[4][4], bh[4][2], bl[4][2];
#pragma unroll
            for (int mt = 0; mt < 4; ++mt) {
                const int r0 = (warp_m + mt * 16 + g) * GW_LDS + off;
                ah[mt][0] = AhS[r0];
                ah[mt][1] = AhS[r0 + 8 * GW_LDS];
                ah[mt][2] = AhS[r0 + 4];
                ah[mt][3] = AhS[r0 + 8 * GW_LDS + 4];
                al[mt][0] = AlS[r0];
                al[mt][1] = AlS[r0 + 8 * GW_LDS];
                al[mt][2] = AlS[r0 + 4];
                al[mt][3] = AlS[r0 + 8 * GW_LDS + 4];
            }
#pragma unroll
            for (int nt = 0; nt < 4; ++nt) {
                const int n0 = (warp_n + nt * 8 + g) * GW_LDS + off;
                bh[nt][0] = BhS[n0]; bh[nt][1] = BhS[n0 + 4];
                bl[nt][0] = BlS[n0]; bl[nt][1] = BlS[n0 + 4];
            }
#pragma unroll
            for (int mt = 0; mt < 4; ++mt)
#pragma unroll
                for (int nt = 0; nt < 4; ++nt)
                    mma_bf16(c[mt][nt], ah[mt], bh[nt]);
#pragma unroll
            for (int mt = 0; mt < 4; ++mt)
#pragma unroll
                for (int nt = 0; nt < 4; ++nt)
                    mma_bf16(c[mt][nt], ah[mt], bl[nt]);
#pragma unroll
            for (int mt = 0; mt < 4; ++mt)
#pragma unroll
                for (int nt = 0; nt < 4; ++nt)
                    mma_bf16(c[mt][nt], al[mt], bh[nt]);
        }

        // ---- split+store prefetched chunk into the other stage ----
        if (ch < 63) {
            uint32_t* AhN = gsm32 + (size_t)(s ^ 1) * (4 * GW_TILE);
            uint32_t* AlN = AhN + GW_TILE;
            uint32_t* BhN = AlN + GW_TILE;
            uint32_t* BlN = BhN + GW_TILE;
#pragma unroll
            for (int i = 0; i < 4; ++i) {
                float4 va = apf[i];
                if (fixA) {
                    va.x = nn_fix(va.x); va.y = nn_fix(va.y);
                    va.z = nn_fix(va.z); va.w = nn_fix(va.w);
                }
                uint2 hw, lw;
                split4(va, hw, lw);
                *(uint2*)&AhN[wbase + 2 * i] = hw;
                *(uint2*)&AlN[wbase + 2 * i] = lw;
                split4(bpf[i], hw, lw);
                *(uint2*)&BhN[wbase + 2 * i] = hw;
                *(uint2*)&BlN[wbase + 2 * i] = lw;
            }
        }
    }

    // ---- epilogue ----
#pragma unroll
    for (int mt = 0; mt < 4; ++mt) {
        const int row0 = bm * 128 + warp_m + mt * 16 + g;
#pragma unroll
        for (int nt = 0; nt < 4; ++nt) {
            const int coln = warp_n + nt * 8 + 2 * tig;
            if (mode == 3) {
                float* d0 = Cext + (size_t)row0 * 2048 + bn * 128 + coln;
                float* d1 = Cext + (size_t)(row0 + 8) * 2048 + bn * 128 + coln;
                d0[0] = nn_fix(c[mt][nt][0]); d0[1] = nn_fix(c[mt][nt][1]);
                d1[0] = nn_fix(c[mt][nt][2]); d1[1] = nn_fix(c[mt][nt][3]);
            } else {
                float* Cg = (mode == 0) ? g_q : (mode == 1) ? g_k : g_v;
                float* base = Cg + (size_t)bn * (TSEQ * HDIM);
                *(float2*)&base[(size_t)row0 * HDIM + coln] =
                    make_float2(c[mt][nt][0], c[mt][nt][1]);
                *(float2*)&base[(size_t)(row0 + 8) * HDIM + coln] =
                    make_float2(c[mt][nt][2], c[mt][nt][3]);
            }
        }
    }
}

// ---------------- RoPE in-place on g_q, g_k ----------------------------------
__global__ void rope_kernel()
{
    const int t = blockIdx.x;      // 0..2047
    const int i = threadIdx.x;     // 0..63 (pair index)
    const float pw = (float)pow(10000.0, (double)(2 * i) / 128.0);
    const float inv = 1.0f / pw;
    const float freq = (float)t * inv;
    const float c = cosf(freq);
    const float s = sinf(freq);
#pragma unroll 4
    for (int h = 0; h < NHEAD; ++h) {
        float* q = g_q + ((size_t)(h * TSEQ + t)) * HDIM;
        float x1 = q[i], x2 = q[i + 64];
        q[i]      = __fadd_rn(__fmul_rn(x1, c), __fmul_rn(-x2, s));
        q[i + 64] = __fadd_rn(__fmul_rn(x2, c), __fmul_rn(x1, s));
        float* k = g_k + ((size_t)(h * TSEQ + t)) * HDIM;
        float y1 = k[i], y2 = k[i + 64];
        k[i]      = __fadd_rn(__fmul_rn(y1, c), __fmul_rn(-y2, s));
        k[i + 64] = __fadd_rn(__fmul_rn(y2, c), __fmul_rn(y1, s));
    }
}

// ---------------- threefry-2x32, PARTITIONABLE path --------------------------
__device__ __forceinline__ unsigned rotl32(unsigned x, int d) {
    return (x << d) | (x >> (32 - d));
}

__device__ float jax_uniform42_partitionable(int h)
{
    const unsigned k0 = 0u, k1 = 42u;
    const unsigned k2 = k0 ^ k1 ^ 0x1BD11BDAu;
    const unsigned ks[3] = { k0, k1, k2 };
    unsigned x0 = 0u + k0;              // counter hi = 0
    unsigned x1 = (unsigned)h + k1;     // counter lo = h
    const int rotA[4] = { 13, 15, 26, 6 };
    const int rotB[4] = { 17, 29, 16, 24 };
#pragma unroll
    for (int i = 0; i < 5; ++i) {
        const int* R = (i & 1) ? rotB : rotA;
#pragma unroll
        for (int j = 0; j < 4; ++j) {
            x0 += x1;
            x1 = rotl32(x1, R[j]);
            x1 ^= x0;
        }
        x0 += ks[(i + 1) % 3];
        x1 += ks[(i + 2) % 3] + (unsigned)(i + 1);
    }
    const unsigned bits = x0 ^ x1;
    return __uint_as_float((bits >> 9) | 0x3f800000u) - 1.0f;
}

// ---------------- last-row stats: p, bern, v_e per head ----------------------
__global__ void __launch_bounds__(256) lastrow_kernel()
{
    const int h = blockIdx.x;
    const int tid = threadIdx.x;
    __shared__ float qv[128];
    __shared__ float s[2048];
    __shared__ float red[256];
    __shared__ float red2[256];
    __shared__ float sh_scale;

    if (tid < 128) qv[tid] = g_q[((size_t)h * TSEQ + 2047) * HDIM + tid];
    __syncthreads();

    for (int k = tid; k < 2048; k += 256) {
        const bool keep = (k < 204) || (k >= 1229);
        float val = -INFINITY;
        if (keep) {
            const float4* kr = (const float4*)(g_k + ((size_t)h * TSEQ + k) * HDIM);
            const float4* q4 = (const float4*)qv;
            float dot = 0.0f;
#pragma unroll
            for (int d4 = 0; d4 < 32; ++d4) {
                float4 a = q4[d4]; float4 b = kr[d4];
                dot = fmaf(a.x, b.x, dot); dot = fmaf(a.y, b.y, dot);
                dot = fmaf(a.z, b.z, dot); dot = fmaf(a.w, b.w, dot);
            }
            val = dot / 11.313708498984760f;  // / sqrt(128)
        }
        s[k] = val;
    }
    __syncthreads();

    float lm = -INFINITY;
    for (int k = tid; k < 2048; k += 256) lm = fmaxf(lm, s[k]);
    red[tid] = lm;
    __syncthreads();
    for (int st = 128; st > 0; st >>= 1) {
        if (tid < st) red[tid] = fmaxf(red[tid], red[tid + st]);
        __syncthreads();
    }
    const float m = red[0];
    __syncthreads();

    float ls = 0.0f, lrS = 0.0f;
    for (int k = tid; k < 2048; k += 256) {
        if ((k < 204) || (k >= 1229)) {
            const float e = expf(s[k] - m);
            ls += e;
            if (k >= 1230) lrS += e;
        }
    }
    red[tid] = ls; red2[tid] = lrS;
    __syncthreads();
    for (int st = 128; st > 0; st >>= 1) {
        if (tid < st) { red[tid] += red[tid + st]; red2[tid] += red2[tid + st]; }
        __syncthreads();
    }
    if (tid == 0) {
        const float L = red[0], R = red2[0];
        const float Pev = expf(s[1229] - m) / L;
        const float mean = (R / L) / 818.0f + 1e-6f;
        float p = Pev / mean;
        if (isnan(p)) p = 0.0f;
        p = fminf(fmaxf(p, 0.0f), 1.0f);
        const float u = jax_uniform42_partitionable(h);
        sh_scale = (u < p) ? 1.0f : 0.0f;
    }
    __syncthreads();
    if (tid < 128)
        g_ve[h * HDIM + tid] =
            (g_v[((size_t)h * TSEQ + 1229) * HDIM + tid] * sh_scale) / 819.0f;
}

// ---------------- flash-style attention over kept K columns ------------------
// (R5 scalar version — proven fastest FFMA formulation)
#define ATTN_SMEM_FLOATS (64*129 + 64*129 + 64*132 + 64*66 + 256)
#define ATTN_SMEM_BYTES  (ATTN_SMEM_FLOATS * 4)

__global__ void __launch_bounds__(256) attn_kernel()
{
    extern __shared__ float sm[];
    float* Qs   = sm;
    float* Ks   = Qs + 64 * 129;
    float* Vs   = Ks + 64 * 129;
    float* S    = Vs + 64 * 132;
    float* m_s  = S + 64 * 66;
    float* l_s  = m_s + 64;
    float* lr_s = l_s + 64;
    float* fac_s = lr_s + 64;

    const int h   = blockIdx.y;
    const int qt  = blockIdx.x;
    const int tid = threadIdx.x;
    const int ty  = tid >> 4;
    const int tx  = tid & 15;
    const int r0  = ty << 2;
    const int cS0 = tx << 2;
    const int cV0 = tx << 3;

    const int ldr = tid >> 5;
    const int ldc = (tid & 31) << 2;

    const float* qbase = g_q + ((size_t)h * TSEQ + qt * 64) * HDIM;
#pragma unroll
    for (int it = 0; it < 8; ++it) {
        const int j = ldr + it * 8;
        float4 v = *(const float4*)(qbase + (size_t)j * HDIM + ldc);
        Qs[j * 129 + ldc + 0] = v.x; Qs[j * 129 + ldc + 1] = v.y;
        Qs[j * 129 + ldc + 2] = v.z; Qs[j * 129 + ldc + 3] = v.w;
    }
    if (tid < 64) { m_s[tid] = -INFINITY; l_s[tid] = 0.0f; lr_s[tid] = 0.0f; }

    float acc[4][8];
#pragma unroll
    for (int i = 0; i < 4; ++i)
#pragma unroll
        for (int j = 0; j < 8; ++j) acc[i][j] = 0.0f;

    __syncthreads();

    for (int tile = 0; tile < 17; ++tile) {
        const int kb   = (tile < 4) ? tile * 64 : 1229 + (tile - 4) * 64;
        const int kend = (tile < 4) ? 204 : 2048;

#pragma unroll
        for (int it = 0; it < 8; ++it) {
            const int j = ldr + it * 8;
            const int kc = kb + j;
            float4 kv = make_float4(0.f, 0.f, 0.f, 0.f);
            float4 vv = kv;
            if (kc < kend) {
                kv = *(const float4*)(g_k + ((size_t)h * TSEQ + kc) * HDIM + ldc);
                vv = *(const float4*)(g_v + ((size_t)h * TSEQ + kc) * HDIM + ldc);
            }
            Ks[j * 129 + ldc + 0] = kv.x; Ks[j * 129 + ldc + 1] = kv.y;
            Ks[j * 129 + ldc + 2] = kv.z; Ks[j * 129 + ldc + 3] = kv.w;
            *(float4*)&Vs[j * 132 + ldc] = vv;
        }
        __syncthreads();

        float sacc[4][4];
#pragma unroll
        for (int i = 0; i < 4; ++i)
#pragma unroll
            for (int j = 0; j < 4; ++j) sacc[i][j] = 0.0f;

        const float* q0 = Qs + (r0 + 0) * 129;
        const float* q1 = Qs + (r0 + 1) * 129;
        const float* q2 = Qs + (r0 + 2) * 129;
        const float* q3 = Qs + (r0 + 3) * 129;
        const float* kp0 = Ks + (cS0 + 0) * 129;
        const float* kp1 = Ks + (cS0 + 1) * 129;
        const float* kp2 = Ks + (cS0 + 2) * 129;
        const float* kp3 = Ks + (cS0 + 3) * 129;
#pragma unroll 8
        for (int kk = 0; kk < 128; ++kk) {
            const float a0 = q0[kk], a1 = q1[kk], a2 = q2[kk], a3 = q3[kk];
            const float b0 = kp0[kk], b1 = kp1[kk], b2 = kp2[kk], b3 = kp3[kk];
            sacc[0][0] = fmaf(a0, b0, sacc[0][0]); sacc[0][1] = fmaf(a0, b1, sacc[0][1]);
            sacc[0][2] = fmaf(a0, b2, sacc[0][2]); sacc[0][3] = fmaf(a0, b3, sacc[0][3]);
            sacc[1][0] = fmaf(a1, b0, sacc[1][0]); sacc[1][1] = fmaf(a1, b1, sacc[1][1]);
            sacc[1][2] = fmaf(a1, b2, sacc[1][2]); sacc[1][3] = fmaf(a1, b3, sacc[1][3]);
            sacc[2][0] = fmaf(a2, b0, sacc[2][0]); sacc[2][1] = fmaf(a2, b1, sacc[2][1]);
            sacc[2][2] = fmaf(a2, b2, sacc[2][2]); sacc[2][3] = fmaf(a2, b3, sacc[2][3]);
            sacc[3][0] = fmaf(a3, b0, sacc[3][0]); sacc[3][1] = fmaf(a3, b1, sacc[3][1]);
            sacc[3][2] = fmaf(a3, b2, sacc[3][2]); sacc[3][3] = fmaf(a3, b3, sacc[3][3]);
        }
#pragma unroll
        for (int i = 0; i < 4; ++i)
#pragma unroll
            for (int j = 0; j < 4; ++j) {
                const int kc = kb + cS0 + j;
                S[(r0 + i) * 66 + cS0 + j] =
                    (kc < kend) ? sacc[i][j] / 11.313708498984760f : -1e30f;
            }
        __syncthreads();

        if (tid < 64) {
            const int r = tid;
            float* Sr = S + r * 66;
            float tm = -1e30f;
#pragma unroll 8
            for (int j = 0; j < 64; ++j) tm = fmaxf(tm, Sr[j]);
            const float mo = m_s[r];
            const float mn = fmaxf(mo, tm);
            const float fac = expf(mo - mn);
            float sum = 0.0f, sumr = 0.0f;
#pragma unroll 4
            for (int j = 0; j < 64; ++j) {
                const float e = expf(Sr[j] - mn);
                Sr[j] = e;
                sum += e;
                if (kb + j >= 1230) sumr += e;
            }
            l_s[r]  = l_s[r]  * fac + sum;
            lr_s[r] = lr_s[r] * fac + sumr;
            m_s[r]  = mn;
            fac_s[r] = fac;
        }
        __syncthreads();

        {
            const float f0 = fac_s[r0 + 0], f1 = fac_s[r0 + 1];
            const float f2 = fac_s[r0 + 2], f3 = fac_s[r0 + 3];
#pragma unroll
            for (int j = 0; j < 8; ++j) {
                acc[0][j] *= f0; acc[1][j] *= f1; acc[2][j] *= f2; acc[3][j] *= f3;
            }
        }
#pragma unroll 2
        for (int jp = 0; jp < 64; ++jp) {
            const float p0 = S[(r0 + 0) * 66 + jp];
            const float p1 = S[(r0 + 1) * 66 + jp];
            const float p2 = S[(r0 + 2) * 66 + jp];
            const float p3 = S[(r0 + 3) * 66 + jp];
            float vv[8];
            *(float4*)&vv[0] = *(const float4*)&Vs[jp * 132 + cV0];
            *(float4*)&vv[4] = *(const float4*)&Vs[jp * 132 + cV0 + 4];
#pragma unroll
            for (int j = 0; j < 8; ++j) {
                acc[0][j] = fmaf(p0, vv[j], acc[0][j]);
                acc[1][j] = fmaf(p1, vv[j], acc[1][j]);
                acc[2][j] = fmaf(p2, vv[j], acc[2][j]);
                acc[3][j] = fmaf(p3, vv[j], acc[3][j]);
            }
        }
        __syncthreads();
    }

    const int qg0 = qt * 64;
#pragma unroll
    for (int i = 0; i < 4; ++i) {
        const int r = r0 + i;
        const int qrow = qg0 + r;
        const float linv = 1.0f / l_s[r];
        const float corr = (qrow >= 1792) ? lr_s[r] * linv : 0.0f;
#pragma unroll
        for (int j = 0; j < 8; ++j) {
            const int dcol = cV0 + j;
            const float o = acc[i][j] * linv + corr * g_ve[h * HDIM + dcol];
            g_ctx[(size_t)qrow * 2048 + h * HDIM + dcol] = o;
        }
    }
}

// ---------------- launch ------------------------------------------------------
extern "C" void kernel_launch(void* const* d_in, const int* in_sizes, int n_in,
                              void* d_out, int out_size)
{
    (void)in_sizes; (void)n_in; (void)out_size;
    const float* hs = (const float*)d_in[0];
    const float* Wq = (const float*)d_in[1];
    const float* Wk = (const float*)d_in[2];
    const float* Wv = (const float*)d_in[3];
    const float* Wo = (const float*)d_in[4];
    float* out = (float*)d_out;

    cudaFuncSetAttribute(gemm_tc_kernel,
                         cudaFuncAttributeMaxDynamicSharedMemorySize,
                         G_SMEM_BYTES);
    cudaFuncSetAttribute(attn_kernel,
                         cudaFuncAttributeMaxDynamicSharedMemorySize,
                         ATTN_SMEM_BYTES);

    dim3 ggrid(16, 16);
    gemm_tc_kernel<<<ggrid, 256, G_SMEM_BYTES>>>(hs, Wq, nullptr, 0);
    gemm_tc_kernel<<<ggrid, 256, G_SMEM_BYTES>>>(hs, Wk, nullptr, 1);
    gemm_tc_kernel<<<ggrid, 256, G_SMEM_BYTES>>>(hs, Wv, nullptr, 2);
    rope_kernel<<<2048, 64>>>();
    lastrow_kernel<<<16, 256>>>();
    attn_kernel<<<dim3(32, 16), 256, ATTN_SMEM_BYTES>>>();
    gemm_tc_kernel<<<ggrid, 256, G_SMEM_BYTES>>>(nullptr, Wo, out, 3);
}

// round 13
// speedup vs baseline: 1.3389x; 1.1130x over previous
#include <cuda_runtime.h>
#include <cuda_bf16.h>
#include <math.h>
#include <stdint.h>

// Problem constants
#define TSEQ 2048
#define NHEAD 16
#define HDIM 128
// mask: keep k < 204 or k >= 1229 ; evict = 1229 ; recent rb = 819
// last_start = 1792 ; mean over k in [1230, 2048) -> 818 elements

// ---------------- scratch (static device globals; no allocation) -------------
__device__ float g_q[NHEAD * TSEQ * HDIM];   // [h][t][d], rope applied
__device__ float g_k[NHEAD * TSEQ * HDIM];
__device__ float g_v[NHEAD * TSEQ * HDIM];
__device__ float g_ctx[TSEQ * 2048];         // [t][h*128+d]
__device__ float g_ve[NHEAD * HDIM];         // v_e per head (includes bern/rb)

// nan_to_num(nan=0, posinf=1e4, neginf=-1e4): replaces non-finite ONLY
__device__ __forceinline__ float nn_fix(float x) {
    if (isnan(x)) return 0.0f;
    if (isinf(x)) return x > 0.0f ? 10000.0f : -10000.0f;
    return x;
}

// pack two floats to bf16x2 word (lo in bits[0:16), hi in bits[16:32))
__device__ __forceinline__ uint32_t bf2(float lo, float hi) {
    uint32_t r;
    asm("cvt.rn.bf16x2.f32 %0, %1, %2;" : "=r"(r) : "f"(hi), "f"(lo));
    return r;
}

// bf16x3 split of a float4 (k-pairs (x,y) and (z,w)) -> hi uint2, lo uint2
__device__ __forceinline__ void split4(float4 v, uint2& hw, uint2& lw) {
    const uint32_t h0 = bf2(v.x, v.y);
    const float f0 = __uint_as_float(h0 << 16);
    const float f1 = __uint_as_float(h0 & 0xffff0000u);
    const uint32_t l0 = bf2(v.x - f0, v.y - f1);
    const uint32_t h1 = bf2(v.z, v.w);
    const float f2 = __uint_as_float(h1 << 16);
    const float f3 = __uint_as_float(h1 & 0xffff0000u);
    const uint32_t l1 = bf2(v.z - f2, v.w - f3);
    hw = make_uint2(h0, h1);
    lw = make_uint2(l0, l1);
}

// portable tensor core: mma.sync m16n8k16 bf16, fp32 accumulate
__device__ __forceinline__ void mma_bf16(float* d, const uint32_t* a,
                                         const uint32_t* b) {
    asm volatile(
        "mma.sync.aligned.m16n8k16.row.col.f32.bf16.bf16.f32 "
        "{%0,%1,%2,%3}, {%4,%5,%6,%7}, {%8,%9}, {%0,%1,%2,%3};"
        : "+f"(d[0]), "+f"(d[1]), "+f"(d[2]), "+f"(d[3])
        : "r"(a[0]), "r"(a[1]), "r"(a[2]), "r"(a[3]), "r"(b[0]), "r"(b[1]));
}

// ============ mma.sync BF16x3 GEMM: C[M,N] = A[M,K] * B[N,K]^T ===============
// M=N=K=2048, CTA tile 128x128, 512 threads (16 warps, 4x4), warp tile 32x32.
// 4 warps/SMSP for latency hiding. SMEM: bf16-packed hi/lo tiles, row stride
// 20 words -> fragment LDS.32 conflict-free. Double buffered, 1 sync/chunk.
// mode 0: fused QKV (blockIdx.z selects Wq/Wk/Wv and g_q/g_k/g_v)
// mode 3: ctx @ Wo^T -> Cext with nn_fix
#define GW_LDS 20
#define GW_TILE (128 * GW_LDS)               // u32 per tile
#define G_SMEM_BYTES (2 * 4 * GW_TILE * 4)   // 2 stages x (Ah,Al,Bh,Bl) = 80KB

__global__ void __launch_bounds__(512, 1)
gemm_tc_kernel(const float* __restrict__ Aext,
               const float* __restrict__ B0, const float* __restrict__ B1,
               const float* __restrict__ B2,
               float* __restrict__ Cext, int mode)
{
    extern __shared__ uint32_t gsm32[];
    const int z = blockIdx.z;
    const float* Aglob = (mode == 3) ? (const float*)g_ctx : Aext;
    const float* B = (mode == 3) ? B0 : (z == 0 ? B0 : (z == 1 ? B1 : B2));
    const bool fixA = (mode != 3);

    const int tid  = threadIdx.x;
    const int wid  = tid >> 5;
    const int lane = tid & 31;
    const int g    = lane >> 2;     // fragment row 0..7
    const int tig  = lane & 3;      // fragment col 0..3
    const int bm = blockIdx.y, bn = blockIdx.x;

    const int warp_m = (wid >> 2) * 32;   // 0,32,64,96
    const int warp_n = (wid & 3) * 32;    // 0,32,64,96

    float c[2][4][4];
#pragma unroll
    for (int i = 0; i < 2; ++i)
#pragma unroll
        for (int j = 0; j < 4; ++j)
#pragma unroll
            for (int q = 0; q < 4; ++q) c[i][j][q] = 0.0f;

    const float* Ab = Aglob + (size_t)(bm * 128) * 2048;
    const float* Bb = B + (size_t)(bn * 128) * 2048;

    // GMEM load assignment: 4 threads per row, each thread 8 floats
    const int gr = tid >> 2;            // row 0..127
    const int tq = tid & 3;             // quarter 0..3
    const int gk = tq * 8;              // float offset in chunk
    const int wbase = gr * GW_LDS + tq * 4;   // word base in smem row

    float4 apf[2], bpf[2];
#pragma unroll
    for (int i = 0; i < 2; ++i) {
        apf[i] = *(const float4*)(Ab + (size_t)gr * 2048 + gk + i * 4);
        bpf[i] = *(const float4*)(Bb + (size_t)gr * 2048 + gk + i * 4);
    }
    // ---- chunk 0: split + store to stage 0 ----
    {
        uint32_t* AhS = gsm32;
        uint32_t* AlS = AhS + GW_TILE;
        uint32_t* BhS = AlS + GW_TILE;
        uint32_t* BlS = BhS + GW_TILE;
#pragma unroll
        for (int i = 0; i < 2; ++i) {
            float4 va = apf[i];
            if (fixA) {
                va.x = nn_fix(va.x); va.y = nn_fix(va.y);
                va.z = nn_fix(va.z); va.w = nn_fix(va.w);
            }
            uint2 hw, lw;
            split4(va, hw, lw);
            *(uint2*)&AhS[wbase + 2 * i] = hw;
            *(uint2*)&AlS[wbase + 2 * i] = lw;
            split4(bpf[i], hw, lw);
            *(uint2*)&BhS[wbase + 2 * i] = hw;
            *(uint2*)&BlS[wbase + 2 * i] = lw;
        }
    }

    for (int ch = 0; ch < 64; ++ch) {
        const int s = ch & 1;
        uint32_t* AhS = gsm32 + (size_t)s * (4 * GW_TILE);
        uint32_t* AlS = AhS + GW_TILE;
        uint32_t* BhS = AlS + GW_TILE;
        uint32_t* BlS = BhS + GW_TILE;
        __syncthreads();    // stage s visible; stage s^1 fully consumed

        // prefetch next chunk (overlaps compute below)
        if (ch < 63) {
            const int k0n = (ch + 1) * 32;
#pragma unroll
            for (int i = 0; i < 2; ++i) {
                apf[i] = *(const float4*)(Ab + (size_t)gr * 2048 + k0n + gk + i * 4);
                bpf[i] = *(const float4*)(Bb + (size_t)gr * 2048 + k0n + gk + i * 4);
            }
        }

        // ---- compute: 2 k16-steps, 3 bf16 terms each ----
#pragma unroll
        for (int ks = 0; ks < 2; ++ks) {
            const int off = ks * 8 + tig;
            uint32_t ah[2][4], al[2][4], bh[4][2], bl[4][2];
#pragma unroll
            for (int mt = 0; mt < 2; ++mt) {
                const int r0 = (warp_m + mt * 16 + g) * GW_LDS + off;
                ah[mt][0] = AhS[r0];
                ah[mt][1] = AhS[r0 + 8 * GW_LDS];
                ah[mt][2] = AhS[r0 + 4];
                ah[mt][3] = AhS[r0 + 8 * GW_LDS + 4];
                al[mt][0] = AlS[r0];
                al[mt][1] = AlS[r0 + 8 * GW_LDS];
                al[mt][2] = AlS[r0 + 4];
                al[mt][3] = AlS[r0 + 8 * GW_LDS + 4];
            }
#pragma unroll
            for (int nt = 0; nt < 4; ++nt) {
                const int n0 = (warp_n + nt * 8 + g) * GW_LDS + off;
                bh[nt][0] = BhS[n0]; bh[nt][1] = BhS[n0 + 4];
                bl[nt][0] = BlS[n0]; bl[nt][1] = BlS[n0 + 4];
            }
#pragma unroll
            for (int mt = 0; mt < 2; ++mt)
#pragma unroll
                for (int nt = 0; nt < 4; ++nt)
                    mma_bf16(c[mt][nt], ah[mt], bh[nt]);
#pragma unroll
            for (int mt = 0; mt < 2; ++mt)
#pragma unroll
                for (int nt = 0; nt < 4; ++nt)
                    mma_bf16(c[mt][nt], ah[mt], bl[nt]);
#pragma unroll
            for (int mt = 0; mt < 2; ++mt)
#pragma unroll
                for (int nt = 0; nt < 4; ++nt)
                    mma_bf16(c[mt][nt], al[mt], bh[nt]);
        }

        // ---- split+store prefetched chunk into the other stage ----
        if (ch < 63) {
            uint32_t* AhN = gsm32 + (size_t)(s ^ 1) * (4 * GW_TILE);
            uint32_t* AlN = AhN + GW_TILE;
            uint32_t* BhN = AlN + GW_TILE;
            uint32_t* BlN = BhN + GW_TILE;
#pragma unroll
            for (int i = 0; i < 2; ++i) {
                float4 va = apf[i];
                if (fixA) {
                    va.x = nn_fix(va.x); va.y = nn_fix(va.y);
                    va.z = nn_fix(va.z); va.w = nn_fix(va.w);
                }
                uint2 hw, lw;
                split4(va, hw, lw);
                *(uint2*)&AhN[wbase + 2 * i] = hw;
                *(uint2*)&AlN[wbase + 2 * i] = lw;
                split4(bpf[i], hw, lw);
                *(uint2*)&BhN[wbase + 2 * i] = hw;
                *(uint2*)&BlN[wbase + 2 * i] = lw;
            }
        }
    }

    // ---- epilogue ----
#pragma unroll
    for (int mt = 0; mt < 2; ++mt) {
        const int row0 = bm * 128 + warp_m + mt * 16 + g;
#pragma unroll
        for (int nt = 0; nt < 4; ++nt) {
            const int coln = warp_n + nt * 8 + 2 * tig;
            if (mode == 3) {
                float* d0 = Cext + (size_t)row0 * 2048 + bn * 128 + coln;
                float* d1 = Cext + (size_t)(row0 + 8) * 2048 + bn * 128 + coln;
                d0[0] = nn_fix(c[mt][nt][0]); d0[1] = nn_fix(c[mt][nt][1]);
                d1[0] = nn_fix(c[mt][nt][2]); d1[1] = nn_fix(c[mt][nt][3]);
            } else {
                float* Cg = (z == 0) ? g_q : (z == 1) ? g_k : g_v;
                float* base = Cg + (size_t)bn * (TSEQ * HDIM);
                *(float2*)&base[(size_t)row0 * HDIM + coln] =
                    make_float2(c[mt][nt][0], c[mt][nt][1]);
                *(float2*)&base[(size_t)(row0 + 8) * HDIM + coln] =
                    make_float2(c[mt][nt][2], c[mt][nt][3]);
            }
        }
    }
}

// ---------------- RoPE in-place on g_q, g_k ----------------------------------
__global__ void rope_kernel()
{
    const int t = blockIdx.x;      // 0..2047
    const int i = threadIdx.x;     // 0..63 (pair index)
    const float pw = (float)pow(10000.0, (double)(2 * i) / 128.0);
    const float inv = 1.0f / pw;
    const float freq = (float)t * inv;
    const float c = cosf(freq);
    const float s = sinf(freq);
#pragma unroll 4
    for (int h = 0; h < NHEAD; ++h) {
        float* q = g_q + ((size_t)(h * TSEQ + t)) * HDIM;
        float x1 = q[i], x2 = q[i + 64];
        q[i]      = __fadd_rn(__fmul_rn(x1, c), __fmul_rn(-x2, s));
        q[i + 64] = __fadd_rn(__fmul_rn(x2, c), __fmul_rn(x1, s));
        float* k = g_k + ((size_t)(h * TSEQ + t)) * HDIM;
        float y1 = k[i], y2 = k[i + 64];
        k[i]      = __fadd_rn(__fmul_rn(y1, c), __fmul_rn(-y2, s));
        k[i + 64] = __fadd_rn(__fmul_rn(y2, c), __fmul_rn(y1, s));
    }
}

// ---------------- threefry-2x32, PARTITIONABLE path --------------------------
__device__ __forceinline__ unsigned rotl32(unsigned x, int d) {
    return (x << d) | (x >> (32 - d));
}

__device__ float jax_uniform42_partitionable(int h)
{
    const unsigned k0 = 0u, k1 = 42u;
    const unsigned k2 = k0 ^ k1 ^ 0x1BD11BDAu;
    const unsigned ks[3] = { k0, k1, k2 };
    unsigned x0 = 0u + k0;              // counter hi = 0
    unsigned x1 = (unsigned)h + k1;     // counter lo = h
    const int rotA[4] = { 13, 15, 26, 6 };
    const int rotB[4] = { 17, 29, 16, 24 };
#pragma unroll
    for (int i = 0; i < 5; ++i) {
        const int* R = (i & 1) ? rotB : rotA;
#pragma unroll
        for (int j = 0; j < 4; ++j) {
            x0 += x1;
            x1 = rotl32(x1, R[j]);
            x1 ^= x0;
        }
        x0 += ks[(i + 1) % 3];
        x1 += ks[(i + 2) % 3] + (unsigned)(i + 1);
    }
    const unsigned bits = x0 ^ x1;
    return __uint_as_float((bits >> 9) | 0x3f800000u) - 1.0f;
}

// ---------------- last-row stats: p, bern, v_e per head ----------------------
__global__ void __launch_bounds__(256) lastrow_kernel()
{
    const int h = blockIdx.x;
    const int tid = threadIdx.x;
    __shared__ float qv[128];
    __shared__ float s[2048];
    __shared__ float red[256];
    __shared__ float red2[256];
    __shared__ float sh_scale;

    if (tid < 128) qv[tid] = g_q[((size_t)h * TSEQ + 2047) * HDIM + tid];
    __syncthreads();

    for (int k = tid; k < 2048; k += 256) {
        const bool keep = (k < 204) || (k >= 1229);
        float val = -INFINITY;
        if (keep) {
            const float4* kr = (const float4*)(g_k + ((size_t)h * TSEQ + k) * HDIM);
            const float4* q4 = (const float4*)qv;
            float dot = 0.0f;
#pragma unroll
            for (int d4 = 0; d4 < 32; ++d4) {
                float4 a = q4[d4]; float4 b = kr[d4];
                dot = fmaf(a.x, b.x, dot); dot = fmaf(a.y, b.y, dot);
                dot = fmaf(a.z, b.z, dot); dot = fmaf(a.w, b.w, dot);
            }
            val = dot / 11.313708498984760f;  // / sqrt(128)
        }
        s[k] = val;
    }
    __syncthreads();

    float lm = -INFINITY;
    for (int k = tid; k < 2048; k += 256) lm = fmaxf(lm, s[k]);
    red[tid] = lm;
    __syncthreads();
    for (int st = 128; st > 0; st >>= 1) {
        if (tid < st) red[tid] = fmaxf(red[tid], red[tid + st]);
        __syncthreads();
    }
    const float m = red[0];
    __syncthreads();

    float ls = 0.0f, lrS = 0.0f;
    for (int k = tid; k < 2048; k += 256) {
        if ((k < 204) || (k >= 1229)) {
            const float e = expf(s[k] - m);
            ls += e;
            if (k >= 1230) lrS += e;
        }
    }
    red[tid] = ls; red2[tid] = lrS;
    __syncthreads();
    for (int st = 128; st > 0; st >>= 1) {
        if (tid < st) { red[tid] += red[tid + st]; red2[tid] += red2[tid + st]; }
        __syncthreads();
    }
    if (tid == 0) {
        const float L = red[0], R = red2[0];
        const float Pev = expf(s[1229] - m) / L;
        const float mean = (R / L) / 818.0f + 1e-6f;
        float p = Pev / mean;
        if (isnan(p)) p = 0.0f;
        p = fminf(fmaxf(p, 0.0f), 1.0f);
        const float u = jax_uniform42_partitionable(h);
        sh_scale = (u < p) ? 1.0f : 0.0f;
    }
    __syncthreads();
    if (tid < 128)
        g_ve[h * HDIM + tid] =
            (g_v[((size_t)h * TSEQ + 1229) * HDIM + tid] * sh_scale) / 819.0f;
}

// ---------------- flash-style attention over kept K columns ------------------
// (R5 scalar version — proven fastest FFMA formulation)
#define ATTN_SMEM_FLOATS (64*129 + 64*129 + 64*132 + 64*66 + 256)
#define ATTN_SMEM_BYTES  (ATTN_SMEM_FLOATS * 4)

__global__ void __launch_bounds__(256) attn_kernel()
{
    extern __shared__ float sm[];
    float* Qs   = sm;
    float* Ks   = Qs + 64 * 129;
    float* Vs   = Ks + 64 * 129;
    float* S    = Vs + 64 * 132;
    float* m_s  = S + 64 * 66;
    float* l_s  = m_s + 64;
    float* lr_s = l_s + 64;
    float* fac_s = lr_s + 64;

    const int h   = blockIdx.y;
    const int qt  = blockIdx.x;
    const int tid = threadIdx.x;
    const int ty  = tid >> 4;
    const int tx  = tid & 15;
    const int r0  = ty << 2;
    const int cS0 = tx << 2;
    const int cV0 = tx << 3;

    const int ldr = tid >> 5;
    const int ldc = (tid & 31) << 2;

    const float* qbase = g_q + ((size_t)h * TSEQ + qt * 64) * HDIM;
#pragma unroll
    for (int it = 0; it < 8; ++it) {
        const int j = ldr + it * 8;
        float4 v = *(const float4*)(qbase + (size_t)j * HDIM + ldc);
        Qs[j * 129 + ldc + 0] = v.x; Qs[j * 129 + ldc + 1] = v.y;
        Qs[j * 129 + ldc + 2] = v.z; Qs[j * 129 + ldc + 3] = v.w;
    }
    if (tid < 64) { m_s[tid] = -INFINITY; l_s[tid] = 0.0f; lr_s[tid] = 0.0f; }

    float acc[4][8];
#pragma unroll
    for (int i = 0; i < 4; ++i)
#pragma unroll
        for (int j = 0; j < 8; ++j) acc[i][j] = 0.0f;

    __syncthreads();

    for (int tile = 0; tile < 17; ++tile) {
        const int kb   = (tile < 4) ? tile * 64 : 1229 + (tile - 4) * 64;
        const int kend = (tile < 4) ? 204 : 2048;

#pragma unroll
        for (int it = 0; it < 8; ++it) {
            const int j = ldr + it * 8;
            const int kc = kb + j;
            float4 kv = make_float4(0.f, 0.f, 0.f, 0.f);
            float4 vv = kv;
            if (kc < kend) {
                kv = *(const float4*)(g_k + ((size_t)h * TSEQ + kc) * HDIM + ldc);
                vv = *(const float4*)(g_v + ((size_t)h * TSEQ + kc) * HDIM + ldc);
            }
            Ks[j * 129 + ldc + 0] = kv.x; Ks[j * 129 + ldc + 1] = kv.y;
            Ks[j * 129 + ldc + 2] = kv.z; Ks[j * 129 + ldc + 3] = kv.w;
            *(float4*)&Vs[j * 132 + ldc] = vv;
        }
        __syncthreads();

        float sacc[4][4];
#pragma unroll
        for (int i = 0; i < 4; ++i)
#pragma unroll
            for (int j = 0; j < 4; ++j) sacc[i][j] = 0.0f;

        const float* q0 = Qs + (r0 + 0) * 129;
        const float* q1 = Qs + (r0 + 1) * 129;
        const float* q2 = Qs + (r0 + 2) * 129;
        const float* q3 = Qs + (r0 + 3) * 129;
        const float* kp0 = Ks + (cS0 + 0) * 129;
        const float* kp1 = Ks + (cS0 + 1) * 129;
        const float* kp2 = Ks + (cS0 + 2) * 129;
        const float* kp3 = Ks + (cS0 + 3) * 129;
#pragma unroll 8
        for (int kk = 0; kk < 128; ++kk) {
            const float a0 = q0[kk], a1 = q1[kk], a2 = q2[kk], a3 = q3[kk];
            const float b0 = kp0[kk], b1 = kp1[kk], b2 = kp2[kk], b3 = kp3[kk];
            sacc[0][0] = fmaf(a0, b0, sacc[0][0]); sacc[0][1] = fmaf(a0, b1, sacc[0][1]);
            sacc[0][2] = fmaf(a0, b2, sacc[0][2]); sacc[0][3] = fmaf(a0, b3, sacc[0][3]);
            sacc[1][0] = fmaf(a1, b0, sacc[1][0]); sacc[1][1] = fmaf(a1, b1, sacc[1][1]);
            sacc[1][2] = fmaf(a1, b2, sacc[1][2]); sacc[1][3] = fmaf(a1, b3, sacc[1][3]);
            sacc[2][0] = fmaf(a2, b0, sacc[2][0]); sacc[2][1] = fmaf(a2, b1, sacc[2][1]);
            sacc[2][2] = fmaf(a2, b2, sacc[2][2]); sacc[2][3] = fmaf(a2, b3, sacc[2][3]);
            sacc[3][0] = fmaf(a3, b0, sacc[3][0]); sacc[3][1] = fmaf(a3, b1, sacc[3][1]);
            sacc[3][2] = fmaf(a3, b2, sacc[3][2]); sacc[3][3] = fmaf(a3, b3, sacc[3][3]);
        }
#pragma unroll
        for (int i = 0; i < 4; ++i)
#pragma unroll
            for (int j = 0; j < 4; ++j) {
                const int kc = kb + cS0 + j;
                S[(r0 + i) * 66 + cS0 + j] =
                    (kc < kend) ? sacc[i][j] / 11.313708498984760f : -1e30f;
            }
        __syncthreads();

        if (tid < 64) {
            const int r = tid;
            float* Sr = S + r * 66;
            float tm = -1e30f;
#pragma unroll 8
            for (int j = 0; j < 64; ++j) tm = fmaxf(tm, Sr[j]);
            const float mo = m_s[r];
            const float mn = fmaxf(mo, tm);
            const float fac = expf(mo - mn);
            float sum = 0.0f, sumr = 0.0f;
#pragma unroll 4
            for (int j = 0; j < 64; ++j) {
                const float e = expf(Sr[j] - mn);
                Sr[j] = e;
                sum += e;
                if (kb + j >= 1230) sumr += e;
            }
            l_s[r]  = l_s[r]  * fac + sum;
            lr_s[r] = lr_s[r] * fac + sumr;
            m_s[r]  = mn;
            fac_s[r] = fac;
        }
        __syncthreads();

        {
            const float f0 = fac_s[r0 + 0], f1 = fac_s[r0 + 1];
            const float f2 = fac_s[r0 + 2], f3 = fac_s[r0 + 3];
#pragma unroll
            for (int j = 0; j < 8; ++j) {
                acc[0][j] *= f0; acc[1][j] *= f1; acc[2][j] *= f2; acc[3][j] *= f3;
            }
        }
#pragma unroll 2
        for (int jp = 0; jp < 64; ++jp) {
            const float p0 = S[(r0 + 0) * 66 + jp];
            const float p1 = S[(r0 + 1) * 66 + jp];
            const float p2 = S[(r0 + 2) * 66 + jp];
            const float p3 = S[(r0 + 3) * 66 + jp];
            float vv[8];
            *(float4*)&vv[0] = *(const float4*)&Vs[jp * 132 + cV0];
            *(float4*)&vv[4] = *(const float4*)&Vs[jp * 132 + cV0 + 4];
#pragma unroll
            for (int j = 0; j < 8; ++j) {
                acc[0][j] = fmaf(p0, vv[j], acc[0][j]);
                acc[1][j] = fmaf(p1, vv[j], acc[1][j]);
                acc[2][j] = fmaf(p2, vv[j], acc[2][j]);
                acc[3][j] = fmaf(p3, vv[j], acc[3][j]);
            }
        }
        __syncthreads();
    }

    const int qg0 = qt * 64;
#pragma unroll
    for (int i = 0; i < 4; ++i) {
        const int r = r0 + i;
        const int qrow = qg0 + r;
        const float linv = 1.0f / l_s[r];
        const float corr = (qrow >= 1792) ? lr_s[r] * linv : 0.0f;
#pragma unroll
        for (int j = 0; j < 8; ++j) {
            const int dcol = cV0 + j;
            const float o = acc[i][j] * linv + corr * g_ve[h * HDIM + dcol];
            g_ctx[(size_t)qrow * 2048 + h * HDIM + dcol] = o;
        }
    }
}

// ---------------- launch ------------------------------------------------------
extern "C" void kernel_launch(void* const* d_in, const int* in_sizes, int n_in,
                              void* d_out, int out_size)
{
    (void)in_sizes; (void)n_in; (void)out_size;
    const float* hs = (const float*)d_in[0];
    const float* Wq = (const float*)d_in[1];
    const float* Wk = (const float*)d_in[2];
    const float* Wv = (const float*)d_in[3];
    const float* Wo = (const float*)d_in[4];
    float* out = (float*)d_out;

    cudaFuncSetAttribute(gemm_tc_kernel,
                         cudaFuncAttributeMaxDynamicSharedMemorySize,
                         G_SMEM_BYTES);
    cudaFuncSetAttribute(attn_kernel,
                         cudaFuncAttributeMaxDynamicSharedMemorySize,
                         ATTN_SMEM_BYTES);

    // fused QKV: z selects Wq/Wk/Wv -> g_q/g_k/g_v
    gemm_tc_kernel<<<dim3(16, 16, 3), 512, G_SMEM_BYTES>>>(
        hs, Wq, Wk, Wv, nullptr, 0);
    rope_kernel<<<2048, 64>>>();
    lastrow_kernel<<<16, 256>>>();
    attn_kernel<<<dim3(32, 16), 256, ATTN_SMEM_BYTES>>>();
    gemm_tc_kernel<<<dim3(16, 16, 1), 512, G_SMEM_BYTES>>>(
        nullptr, Wo, Wo, Wo, out, 3);
}

// round 14
// speedup vs baseline: 1.6925x; 1.2641x over previous
#include <cuda_runtime.h>
#include <cuda_bf16.h>
#include <math.h>
#include <stdint.h>

// Problem constants
#define TSEQ 2048
#define NHEAD 16
#define HDIM 128
// mask: keep k < 204 or k >= 1229 ; evict = 1229 ; recent rb = 819
// last_start = 1792 ; mean over k in [1230, 2048) -> 818 elements

// ---------------- scratch (static device globals; no allocation) -------------
__device__ float g_q[NHEAD * TSEQ * HDIM];   // [h][t][d], rope applied
__device__ float g_k[NHEAD * TSEQ * HDIM];
__device__ float g_v[NHEAD * TSEQ * HDIM];
__device__ float g_ctx[TSEQ * 2048];         // [t][h*128+d]
__device__ float g_ve[NHEAD * HDIM];         // v_e per head (includes bern/rb)

// nan_to_num(nan=0, posinf=1e4, neginf=-1e4): replaces non-finite ONLY
__device__ __forceinline__ float nn_fix(float x) {
    if (isnan(x)) return 0.0f;
    if (isinf(x)) return x > 0.0f ? 10000.0f : -10000.0f;
    return x;
}

// pack two floats to bf16x2 word (f0 in bits[0:16), f1 in bits[16:32))
__device__ __forceinline__ uint32_t bf2(float f0, float f1) {
    uint32_t r;
    asm("cvt.rn.bf16x2.f32 %0, %1, %2;" : "=r"(r) : "f"(f1), "f"(f0));
    return r;
}

// split two fp32 into hi word + residual lo word
__device__ __forceinline__ uint32_t split2(float f0, float f1, uint32_t& lo) {
    const uint32_t h = bf2(f0, f1);
    lo = bf2(f0 - __uint_as_float(h << 16),
             f1 - __uint_as_float(h & 0xffff0000u));
    return h;
}

// bf16x3 split of a float4 (pairs (x,y),(z,w)) -> hi uint2, lo uint2
__device__ __forceinline__ void split4(float4 v, uint2& hw, uint2& lw) {
    uint32_t l0, l1;
    const uint32_t h0 = split2(v.x, v.y, l0);
    const uint32_t h1 = split2(v.z, v.w, l1);
    hw = make_uint2(h0, h1);
    lw = make_uint2(l0, l1);
}

// portable tensor core: mma.sync m16n8k16 bf16, fp32 accumulate
__device__ __forceinline__ void mma_bf16(float* d, const uint32_t* a,
                                         const uint32_t* b) {
    asm volatile(
        "mma.sync.aligned.m16n8k16.row.col.f32.bf16.bf16.f32 "
        "{%0,%1,%2,%3}, {%4,%5,%6,%7}, {%8,%9}, {%0,%1,%2,%3};"
        : "+f"(d[0]), "+f"(d[1]), "+f"(d[2]), "+f"(d[3])
        : "r"(a[0]), "r"(a[1]), "r"(a[2]), "r"(a[3]), "r"(b[0]), "r"(b[1]));
}

// ============ mma.sync BF16x3 GEMM: C[M,N] = A[M,K] * B[N,K]^T ===============
// (R13 version — 512 threads, fused QKV, unchanged)
#define GW_LDS 20
#define GW_TILE (128 * GW_LDS)
#define G_SMEM_BYTES (2 * 4 * GW_TILE * 4)

__global__ void __launch_bounds__(512, 1)
gemm_tc_kernel(const float* __restrict__ Aext,
               const float* __restrict__ B0, const float* __restrict__ B1,
               const float* __restrict__ B2,
               float* __restrict__ Cext, int mode)
{
    extern __shared__ uint32_t gsm32[];
    const int z = blockIdx.z;
    const float* Aglob = (mode == 3) ? (const float*)g_ctx : Aext;
    const float* B = (mode == 3) ? B0 : (z == 0 ? B0 : (z == 1 ? B1 : B2));
    const bool fixA = (mode != 3);

    const int tid  = threadIdx.x;
    const int wid  = tid >> 5;
    const int lane = tid & 31;
    const int g    = lane >> 2;
    const int tig  = lane & 3;
    const int bm = blockIdx.y, bn = blockIdx.x;

    const int warp_m = (wid >> 2) * 32;
    const int warp_n = (wid & 3) * 32;

    float c[2][4][4];
#pragma unroll
    for (int i = 0; i < 2; ++i)
#pragma unroll
        for (int j = 0; j < 4; ++j)
#pragma unroll
            for (int q = 0; q < 4; ++q) c[i][j][q] = 0.0f;

    const float* Ab = Aglob + (size_t)(bm * 128) * 2048;
    const float* Bb = B + (size_t)(bn * 128) * 2048;

    const int gr = tid >> 2;
    const int tq = tid & 3;
    const int gk = tq * 8;
    const int wbase = gr * GW_LDS + tq * 4;

    float4 apf[2], bpf[2];
#pragma unroll
    for (int i = 0; i < 2; ++i) {
        apf[i] = *(const float4*)(Ab + (size_t)gr * 2048 + gk + i * 4);
        bpf[i] = *(const float4*)(Bb + (size_t)gr * 2048 + gk + i * 4);
    }
    {
        uint32_t* AhS = gsm32;
        uint32_t* AlS = AhS + GW_TILE;
        uint32_t* BhS = AlS + GW_TILE;
        uint32_t* BlS = BhS + GW_TILE;
#pragma unroll
        for (int i = 0; i < 2; ++i) {
            float4 va = apf[i];
            if (fixA) {
                va.x = nn_fix(va.x); va.y = nn_fix(va.y);
                va.z = nn_fix(va.z); va.w = nn_fix(va.w);
            }
            uint2 hw, lw;
            split4(va, hw, lw);
            *(uint2*)&AhS[wbase + 2 * i] = hw;
            *(uint2*)&AlS[wbase + 2 * i] = lw;
            split4(bpf[i], hw, lw);
            *(uint2*)&BhS[wbase + 2 * i] = hw;
            *(uint2*)&BlS[wbase + 2 * i] = lw;
        }
    }

    for (int ch = 0; ch < 64; ++ch) {
        const int s = ch & 1;
        uint32_t* AhS = gsm32 + (size_t)s * (4 * GW_TILE);
        uint32_t* AlS = AhS + GW_TILE;
        uint32_t* BhS = AlS + GW_TILE;
        uint32_t* BlS = BhS + GW_TILE;
        __syncthreads();

        if (ch < 63) {
            const int k0n = (ch + 1) * 32;
#pragma unroll
            for (int i = 0; i < 2; ++i) {
                apf[i] = *(const float4*)(Ab + (size_t)gr * 2048 + k0n + gk + i * 4);
                bpf[i] = *(const float4*)(Bb + (size_t)gr * 2048 + k0n + gk + i * 4);
            }
        }

#pragma unroll
        for (int ks = 0; ks < 2; ++ks) {
            const int off = ks * 8 + tig;
            uint32_t ah[2][4], al[2][4], bh[4][2], bl[4][2];
#pragma unroll
            for (int mt = 0; mt < 2; ++mt) {
                const int r0 = (warp_m + mt * 16 + g) * GW_LDS + off;
                ah[mt][0] = AhS[r0];
                ah[mt][1] = AhS[r0 + 8 * GW_LDS];
                ah[mt][2] = AhS[r0 + 4];
                ah[mt][3] = AhS[r0 + 8 * GW_LDS + 4];
                al[mt][0] = AlS[r0];
                al[mt][1] = AlS[r0 + 8 * GW_LDS];
                al[mt][2] = AlS[r0 + 4];
                al[mt][3] = AlS[r0 + 8 * GW_LDS + 4];
            }
#pragma unroll
            for (int nt = 0; nt < 4; ++nt) {
                const int n0 = (warp_n + nt * 8 + g) * GW_LDS + off;
                bh[nt][0] = BhS[n0]; bh[nt][1] = BhS[n0 + 4];
                bl[nt][0] = BlS[n0]; bl[nt][1] = BlS[n0 + 4];
            }
#pragma unroll
            for (int mt = 0; mt < 2; ++mt)
#pragma unroll
                for (int nt = 0; nt < 4; ++nt)
                    mma_bf16(c[mt][nt], ah[mt], bh[nt]);
#pragma unroll
            for (int mt = 0; mt < 2; ++mt)
#pragma unroll
                for (int nt = 0; nt < 4; ++nt)
                    mma_bf16(c[mt][nt], ah[mt], bl[nt]);
#pragma unroll
            for (int mt = 0; mt < 2; ++mt)
#pragma unroll
                for (int nt = 0; nt < 4; ++nt)
                    mma_bf16(c[mt][nt], al[mt], bh[nt]);
        }

        if (ch < 63) {
            uint32_t* AhN = gsm32 + (size_t)(s ^ 1) * (4 * GW_TILE);
            uint32_t* AlN = AhN + GW_TILE;
            uint32_t* BhN = AlN + GW_TILE;
            uint32_t* BlN = BhN + GW_TILE;
#pragma unroll
            for (int i = 0; i < 2; ++i) {
                float4 va = apf[i];
                if (fixA) {
                    va.x = nn_fix(va.x); va.y = nn_fix(va.y);
                    va.z = nn_fix(va.z); va.w = nn_fix(va.w);
                }
                uint2 hw, lw;
                split4(va, hw, lw);
                *(uint2*)&AhN[wbase + 2 * i] = hw;
                *(uint2*)&AlN[wbase + 2 * i] = lw;
                split4(bpf[i], hw, lw);
                *(uint2*)&BhN[wbase + 2 * i] = hw;
                *(uint2*)&BlN[wbase + 2 * i] = lw;
            }
        }
    }

#pragma unroll
    for (int mt = 0; mt < 2; ++mt) {
        const int row0 = bm * 128 + warp_m + mt * 16 + g;
#pragma unroll
        for (int nt = 0; nt < 4; ++nt) {
            const int coln = warp_n + nt * 8 + 2 * tig;
            if (mode == 3) {
                float* d0 = Cext + (size_t)row0 * 2048 + bn * 128 + coln;
                float* d1 = Cext + (size_t)(row0 + 8) * 2048 + bn * 128 + coln;
                d0[0] = nn_fix(c[mt][nt][0]); d0[1] = nn_fix(c[mt][nt][1]);
                d1[0] = nn_fix(c[mt][nt][2]); d1[1] = nn_fix(c[mt][nt][3]);
            } else {
                float* Cg = (z == 0) ? g_q : (z == 1) ? g_k : g_v;
                float* base = Cg + (size_t)bn * (TSEQ * HDIM);
                *(float2*)&base[(size_t)row0 * HDIM + coln] =
                    make_float2(c[mt][nt][0], c[mt][nt][1]);
                *(float2*)&base[(size_t)(row0 + 8) * HDIM + coln] =
                    make_float2(c[mt][nt][2], c[mt][nt][3]);
            }
        }
    }
}

// ---------------- RoPE in-place on g_q, g_k ----------------------------------
__global__ void rope_kernel()
{
    const int t = blockIdx.x;
    const int i = threadIdx.x;
    const float pw = (float)pow(10000.0, (double)(2 * i) / 128.0);
    const float inv = 1.0f / pw;
    const float freq = (float)t * inv;
    const float c = cosf(freq);
    const float s = sinf(freq);
#pragma unroll 4
    for (int h = 0; h < NHEAD; ++h) {
        float* q = g_q + ((size_t)(h * TSEQ + t)) * HDIM;
        float x1 = q[i], x2 = q[i + 64];
        q[i]      = __fadd_rn(__fmul_rn(x1, c), __fmul_rn(-x2, s));
        q[i + 64] = __fadd_rn(__fmul_rn(x2, c), __fmul_rn(x1, s));
        float* k = g_k + ((size_t)(h * TSEQ + t)) * HDIM;
        float y1 = k[i], y2 = k[i + 64];
        k[i]      = __fadd_rn(__fmul_rn(y1, c), __fmul_rn(-y2, s));
        k[i + 64] = __fadd_rn(__fmul_rn(y2, c), __fmul_rn(y1, s));
    }
}

// ---------------- threefry-2x32, PARTITIONABLE path --------------------------
__device__ __forceinline__ unsigned rotl32(unsigned x, int d) {
    return (x << d) | (x >> (32 - d));
}

__device__ float jax_uniform42_partitionable(int h)
{
    const unsigned k0 = 0u, k1 = 42u;
    const unsigned k2 = k0 ^ k1 ^ 0x1BD11BDAu;
    const unsigned ks[3] = { k0, k1, k2 };
    unsigned x0 = 0u + k0;
    unsigned x1 = (unsigned)h + k1;
    const int rotA[4] = { 13, 15, 26, 6 };
    const int rotB[4] = { 17, 29, 16, 24 };
#pragma unroll
    for (int i = 0; i < 5; ++i) {
        const int* R = (i & 1) ? rotB : rotA;
#pragma unroll
        for (int j = 0; j < 4; ++j) {
            x0 += x1;
            x1 = rotl32(x1, R[j]);
            x1 ^= x0;
        }
        x0 += ks[(i + 1) % 3];
        x1 += ks[(i + 2) % 3] + (unsigned)(i + 1);
    }
    const unsigned bits = x0 ^ x1;
    return __uint_as_float((bits >> 9) | 0x3f800000u) - 1.0f;
}

// ---------------- last-row stats: p, bern, v_e per head ----------------------
__global__ void __launch_bounds__(256) lastrow_kernel()
{
    const int h = blockIdx.x;
    const int tid = threadIdx.x;
    __shared__ float qv[128];
    __shared__ float s[2048];
    __shared__ float red[256];
    __shared__ float red2[256];
    __shared__ float sh_scale;

    if (tid < 128) qv[tid] = g_q[((size_t)h * TSEQ + 2047) * HDIM + tid];
    __syncthreads();

    for (int k = tid; k < 2048; k += 256) {
        const bool keep = (k < 204) || (k >= 1229);
        float val = -INFINITY;
        if (keep) {
            const float4* kr = (const float4*)(g_k + ((size_t)h * TSEQ + k) * HDIM);
            const float4* q4 = (const float4*)qv;
            float dot = 0.0f;
#pragma unroll
            for (int d4 = 0; d4 < 32; ++d4) {
                float4 a = q4[d4]; float4 b = kr[d4];
                dot = fmaf(a.x, b.x, dot); dot = fmaf(a.y, b.y, dot);
                dot = fmaf(a.z, b.z, dot); dot = fmaf(a.w, b.w, dot);
            }
            val = dot / 11.313708498984760f;
        }
        s[k] = val;
    }
    __syncthreads();

    float lm = -INFINITY;
    for (int k = tid; k < 2048; k += 256) lm = fmaxf(lm, s[k]);
    red[tid] = lm;
    __syncthreads();
    for (int st = 128; st > 0; st >>= 1) {
        if (tid < st) red[tid] = fmaxf(red[tid], red[tid + st]);
        __syncthreads();
    }
    const float m = red[0];
    __syncthreads();

    float ls = 0.0f, lrS = 0.0f;
    for (int k = tid; k < 2048; k += 256) {
        if ((k < 204) || (k >= 1229)) {
            const float e = expf(s[k] - m);
            ls += e;
            if (k >= 1230) lrS += e;
        }
    }
    red[tid] = ls; red2[tid] = lrS;
    __syncthreads();
    for (int st = 128; st > 0; st >>= 1) {
        if (tid < st) { red[tid] += red[tid + st]; red2[tid] += red2[tid + st]; }
        __syncthreads();
    }
    if (tid == 0) {
        const float L = red[0], R = red2[0];
        const float Pev = expf(s[1229] - m) / L;
        const float mean = (R / L) / 818.0f + 1e-6f;
        float p = Pev / mean;
        if (isnan(p)) p = 0.0f;
        p = fminf(fmaxf(p, 0.0f), 1.0f);
        const float u = jax_uniform42_partitionable(h);
        sh_scale = (u < p) ? 1.0f : 0.0f;
    }
    __syncthreads();
    if (tid < 128)
        g_ve[h * HDIM + tid] =
            (g_v[((size_t)h * TSEQ + 1229) * HDIM + tid] * sh_scale) / 819.0f;
}

// ---------------- flash attention, bf16x3 HMMA for QK and PV -----------------
// grid (32 qtiles, 16 heads), 256 threads (8 warps).
// SMEM: Qs/Ks/Vs fp32 [64][132], S fp32 [64][66], stats.
// Warp w: S-tile rows wm=(w>>1)*16, S cols wnS=(w&1)*32 ; O cols wnO=(w&1)*64.
#define ATTN_SMEM_FLOATS (3 * 64 * 132 + 64 * 66 + 256)
#define ATTN_SMEM_BYTES  (ATTN_SMEM_FLOATS * 4)

__global__ void __launch_bounds__(256) attn_kernel()
{
    extern __shared__ float sm[];
    float* Qs   = sm;                  // [64][132]
    float* Ks   = Qs + 64 * 132;       // [64][132]
    float* Vs   = Ks + 64 * 132;       // [64][132]
    float* S    = Vs + 64 * 132;       // [64][66]
    float* m_s  = S + 64 * 66;
    float* l_s  = m_s + 64;
    float* lr_s = l_s + 64;
    float* fac_s = lr_s + 64;

    const int h   = blockIdx.y;
    const int qt  = blockIdx.x;
    const int tid = threadIdx.x;
    const int wid  = tid >> 5;
    const int lane = tid & 31;
    const int g    = lane >> 2;      // fragment row 0..7
    const int tig  = lane & 3;       // fragment col 0..3
    const int wm   = (wid >> 1) * 16;   // 0,16,32,48
    const int wnS  = (wid & 1) * 32;    // S cols
    const int wnO  = (wid & 1) * 64;    // O cols

    const int ldr = tid >> 5;
    const int ldc = (tid & 31) << 2;

    const float* qbase = g_q + ((size_t)h * TSEQ + qt * 64) * HDIM;
#pragma unroll
    for (int it = 0; it < 8; ++it) {
        const int j = ldr + it * 8;
        float4 v = *(const float4*)(qbase + (size_t)j * HDIM + ldc);
        *(float4*)&Qs[j * 132 + ldc] = v;
    }
    if (tid < 64) { m_s[tid] = -INFINITY; l_s[tid] = 0.0f; lr_s[tid] = 0.0f; }

    float oacc[8][4];
#pragma unroll
    for (int i = 0; i < 8; ++i)
#pragma unroll
        for (int j = 0; j < 4; ++j) oacc[i][j] = 0.0f;

    __syncthreads();

    for (int tile = 0; tile < 17; ++tile) {
        const int kb   = (tile < 4) ? tile * 64 : 1229 + (tile - 4) * 64;
        const int kend = (tile < 4) ? 204 : 2048;

#pragma unroll
        for (int it = 0; it < 8; ++it) {
            const int j = ldr + it * 8;
            const int kc = kb + j;
            float4 kv = make_float4(0.f, 0.f, 0.f, 0.f);
            float4 vv = kv;
            if (kc < kend) {
                kv = *(const float4*)(g_k + ((size_t)h * TSEQ + kc) * HDIM + ldc);
                vv = *(const float4*)(g_v + ((size_t)h * TSEQ + kc) * HDIM + ldc);
            }
            *(float4*)&Ks[j * 132 + ldc] = kv;
            *(float4*)&Vs[j * 132 + ldc] = vv;
        }
        __syncthreads();

        // ---- S = Q K^T via bf16x3 HMMA ----
        float sacc[4][4];
#pragma unroll
        for (int nt = 0; nt < 4; ++nt)
#pragma unroll
            for (int q = 0; q < 4; ++q) sacc[nt][q] = 0.0f;

        const int ar0 = (wm + g) * 132;
        const int ar1 = (wm + g + 8) * 132;
#pragma unroll
        for (int ks = 0; ks < 8; ++ks) {
            const int kc0 = ks * 16 + 2 * tig;
            uint32_t ah[4], al[4];
            ah[0] = split2(Qs[ar0 + kc0],     Qs[ar0 + kc0 + 1], al[0]);
            ah[1] = split2(Qs[ar1 + kc0],     Qs[ar1 + kc0 + 1], al[1]);
            ah[2] = split2(Qs[ar0 + kc0 + 8], Qs[ar0 + kc0 + 9], al[2]);
            ah[3] = split2(Qs[ar1 + kc0 + 8], Qs[ar1 + kc0 + 9], al[3]);
            uint32_t bh[4][2], bl[4][2];
#pragma unroll
            for (int nt = 0; nt < 4; ++nt) {
                const int br = (wnS + nt * 8 + g) * 132;
                bh[nt][0] = split2(Ks[br + kc0],     Ks[br + kc0 + 1], bl[nt][0]);
                bh[nt][1] = split2(Ks[br + kc0 + 8], Ks[br + kc0 + 9], bl[nt][1]);
            }
#pragma unroll
            for (int nt = 0; nt < 4; ++nt)
                mma_bf16(sacc[nt], ah, bh[nt]);
#pragma unroll
            for (int nt = 0; nt < 4; ++nt)
                mma_bf16(sacc[nt], ah, bl[nt]);
#pragma unroll
            for (int nt = 0; nt < 4; ++nt)
                mma_bf16(sacc[nt], al, bh[nt]);
        }
        // store with mask + scale
#pragma unroll
        for (int nt = 0; nt < 4; ++nt) {
            const int col = wnS + nt * 8 + 2 * tig;
            const int kc = kb + col;
            S[(wm + g) * 66 + col] =
                (kc < kend) ? sacc[nt][0] / 11.313708498984760f : -1e30f;
            S[(wm + g) * 66 + col + 1] =
                (kc + 1 < kend) ? sacc[nt][1] / 11.313708498984760f : -1e30f;
            S[(wm + g + 8) * 66 + col] =
                (kc < kend) ? sacc[nt][2] / 11.313708498984760f : -1e30f;
            S[(wm + g + 8) * 66 + col + 1] =
                (kc + 1 < kend) ? sacc[nt][3] / 11.313708498984760f : -1e30f;
        }
        __syncthreads();

        // ---- per-row online softmax update (unchanged) ----
        if (tid < 64) {
            const int r = tid;
            float* Sr = S + r * 66;
            float tm = -1e30f;
#pragma unroll 8
            for (int j = 0; j < 64; ++j) tm = fmaxf(tm, Sr[j]);
            const float mo = m_s[r];
            const float mn = fmaxf(mo, tm);
            const float fac = expf(mo - mn);
            float sum = 0.0f, sumr = 0.0f;
#pragma unroll 4
            for (int j = 0; j < 64; ++j) {
                const float e = expf(Sr[j] - mn);
                Sr[j] = e;
                sum += e;
                if (kb + j >= 1230) sumr += e;
            }
            l_s[r]  = l_s[r]  * fac + sum;
            lr_s[r] = lr_s[r] * fac + sumr;
            m_s[r]  = mn;
            fac_s[r] = fac;
        }
        __syncthreads();

        // ---- rescale O fragments, then O += P V via bf16x3 HMMA ----
        {
            const float fA = fac_s[wm + g];
            const float fB = fac_s[wm + g + 8];
#pragma unroll
            for (int nt = 0; nt < 8; ++nt) {
                oacc[nt][0] *= fA; oacc[nt][1] *= fA;
                oacc[nt][2] *= fB; oacc[nt][3] *= fB;
            }
        }
        const int pr0 = (wm + g) * 66;
        const int pr1 = (wm + g + 8) * 66;
#pragma unroll
        for (int ks = 0; ks < 4; ++ks) {
            const int kc0 = ks * 16 + 2 * tig;
            uint32_t ph[4], pl[4];
            ph[0] = split2(S[pr0 + kc0],     S[pr0 + kc0 + 1], pl[0]);
            ph[1] = split2(S[pr1 + kc0],     S[pr1 + kc0 + 1], pl[1]);
            ph[2] = split2(S[pr0 + kc0 + 8], S[pr0 + kc0 + 9], pl[2]);
            ph[3] = split2(S[pr1 + kc0 + 8], S[pr1 + kc0 + 9], pl[3]);
#pragma unroll
            for (int nt = 0; nt < 8; ++nt) {
                const int d = wnO + nt * 8 + g;
                uint32_t vh[2], vl[2];
                vh[0] = split2(Vs[kc0 * 132 + d], Vs[(kc0 + 1) * 132 + d], vl[0]);
                vh[1] = split2(Vs[(kc0 + 8) * 132 + d], Vs[(kc0 + 9) * 132 + d], vl[1]);
                mma_bf16(oacc[nt], ph, vh);
                mma_bf16(oacc[nt], ph, vl);
                mma_bf16(oacc[nt], pl, vh);
            }
        }
        __syncthreads();
    }

    // ---- epilogue: normalize + v_e correction ----
    const int qg0 = qt * 64;
    const int rA = wm + g, rB = wm + g + 8;
    const float linvA = 1.0f / l_s[rA];
    const float linvB = 1.0f / l_s[rB];
    const float corrA = (qg0 + rA >= 1792) ? lr_s[rA] * linvA : 0.0f;
    const float corrB = (qg0 + rB >= 1792) ? lr_s[rB] * linvB : 0.0f;
#pragma unroll
    for (int nt = 0; nt < 8; ++nt) {
        const int col = wnO + nt * 8 + 2 * tig;
        const float ve0 = g_ve[h * HDIM + col];
        const float ve1 = g_ve[h * HDIM + col + 1];
        float* dA = g_ctx + (size_t)(qg0 + rA) * 2048 + h * HDIM + col;
        float* dB = g_ctx + (size_t)(qg0 + rB) * 2048 + h * HDIM + col;
        dA[0] = oacc[nt][0] * linvA + corrA * ve0;
        dA[1] = oacc[nt][1] * linvA + corrA * ve1;
        dB[0] = oacc[nt][2] * linvB + corrB * ve0;
        dB[1] = oacc[nt][3] * linvB + corrB * ve1;
    }
}

// ---------------- launch ------------------------------------------------------
extern "C" void kernel_launch(void* const* d_in, const int* in_sizes, int n_in,
                              void* d_out, int out_size)
{
    (void)in_sizes; (void)n_in; (void)out_size;
    const float* hs = (const float*)d_in[0];
    const float* Wq = (const float*)d_in[1];
    const float* Wk = (const float*)d_in[2];
    const float* Wv = (const float*)d_in[3];
    const float* Wo = (const float*)d_in[4];
    float* out = (float*)d_out;

    cudaFuncSetAttribute(gemm_tc_kernel,
                         cudaFuncAttributeMaxDynamicSharedMemorySize,
                         G_SMEM_BYTES);
    cudaFuncSetAttribute(attn_kernel,
                         cudaFuncAttributeMaxDynamicSharedMemorySize,
                         ATTN_SMEM_BYTES);

    gemm_tc_kernel<<<dim3(16, 16, 3), 512, G_SMEM_BYTES>>>(
        hs, Wq, Wk, Wv, nullptr, 0);
    rope_kernel<<<2048, 64>>>();
    lastrow_kernel<<<16, 256>>>();
    attn_kernel<<<dim3(32, 16), 256, ATTN_SMEM_BYTES>>>();
    gemm_tc_kernel<<<dim3(16, 16, 1), 512, G_SMEM_BYTES>>>(
        nullptr, Wo, Wo, Wo, out, 3);
}

// round 15
// speedup vs baseline: 1.6934x; 1.0005x over previous
#include <cuda_runtime.h>
#include <cuda_bf16.h>
#include <math.h>
#include <stdint.h>

// Problem constants
#define TSEQ 2048
#define NHEAD 16
#define HDIM 128
// mask: keep k < 204 or k >= 1229 ; evict = 1229 ; recent rb = 819
// last_start = 1792 ; mean over k in [1230, 2048) -> 818 elements

// ---------------- scratch (static device globals; no allocation) -------------
__device__ float g_q[NHEAD * TSEQ * HDIM];   // [h][t][d], rope applied
__device__ float g_k[NHEAD * TSEQ * HDIM];
__device__ float g_v[NHEAD * TSEQ * HDIM];
__device__ float g_ctx[TSEQ * 2048];         // [t][h*128+d]
__device__ float g_ve[NHEAD * HDIM];         // v_e per head (includes bern/rb)

// nan_to_num(nan=0, posinf=1e4, neginf=-1e4): replaces non-finite ONLY
__device__ __forceinline__ float nn_fix(float x) {
    if (isnan(x)) return 0.0f;
    if (isinf(x)) return x > 0.0f ? 10000.0f : -10000.0f;
    return x;
}

// pack two floats to bf16x2 word (f0 in bits[0:16), f1 in bits[16:32))
__device__ __forceinline__ uint32_t bf2(float f0, float f1) {
    uint32_t r;
    asm("cvt.rn.bf16x2.f32 %0, %1, %2;" : "=r"(r) : "f"(f1), "f"(f0));
    return r;
}

// split two fp32 into hi word + residual lo word
__device__ __forceinline__ uint32_t split2(float f0, float f1, uint32_t& lo) {
    const uint32_t h = bf2(f0, f1);
    lo = bf2(f0 - __uint_as_float(h << 16),
             f1 - __uint_as_float(h & 0xffff0000u));
    return h;
}

// bf16x3 split of a float4 (pairs (x,y),(z,w)) -> hi uint2, lo uint2
__device__ __forceinline__ void split4(float4 v, uint2& hw, uint2& lw) {
    uint32_t l0, l1;
    const uint32_t h0 = split2(v.x, v.y, l0);
    const uint32_t h1 = split2(v.z, v.w, l1);
    hw = make_uint2(h0, h1);
    lw = make_uint2(l0, l1);
}

// portable tensor core: mma.sync m16n8k16 bf16, fp32 accumulate
__device__ __forceinline__ void mma_bf16(float* d, const uint32_t* a,
                                         const uint32_t* b) {
    asm volatile(
        "mma.sync.aligned.m16n8k16.row.col.f32.bf16.bf16.f32 "
        "{%0,%1,%2,%3}, {%4,%5,%6,%7}, {%8,%9}, {%0,%1,%2,%3};"
        : "+f"(d[0]), "+f"(d[1]), "+f"(d[2]), "+f"(d[3])
        : "r"(a[0]), "r"(a[1]), "r"(a[2]), "r"(a[3]), "r"(b[0]), "r"(b[1]));
}

// ============ mma.sync BF16x3 GEMM: C[M,N] = A[M,K] * B[N,K]^T ===============
// (R13 version — 512 threads, fused QKV, unchanged)
#define GW_LDS 20
#define GW_TILE (128 * GW_LDS)
#define G_SMEM_BYTES (2 * 4 * GW_TILE * 4)

__global__ void __launch_bounds__(512, 1)
gemm_tc_kernel(const float* __restrict__ Aext,
               const float* __restrict__ B0, const float* __restrict__ B1,
               const float* __restrict__ B2,
               float* __restrict__ Cext, int mode)
{
    extern __shared__ uint32_t gsm32[];
    const int z = blockIdx.z;
    const float* Aglob = (mode == 3) ? (const float*)g_ctx : Aext;
    const float* B = (mode == 3) ? B0 : (z == 0 ? B0 : (z == 1 ? B1 : B2));
    const bool fixA = (mode != 3);

    const int tid  = threadIdx.x;
    const int wid  = tid >> 5;
    const int lane = tid & 31;
    const int g    = lane >> 2;
    const int tig  = lane & 3;
    const int bm = blockIdx.y, bn = blockIdx.x;

    const int warp_m = (wid >> 2) * 32;
    const int warp_n = (wid & 3) * 32;

    float c[2][4][4];
#pragma unroll
    for (int i = 0; i < 2; ++i)
#pragma unroll
        for (int j = 0; j < 4; ++j)
#pragma unroll
            for (int q = 0; q < 4; ++q) c[i][j][q] = 0.0f;

    const float* Ab = Aglob + (size_t)(bm * 128) * 2048;
    const float* Bb = B + (size_t)(bn * 128) * 2048;

    const int gr = tid >> 2;
    const int tq = tid & 3;
    const int gk = tq * 8;
    const int wbase = gr * GW_LDS + tq * 4;

    float4 apf[2], bpf[2];
#pragma unroll
    for (int i = 0; i < 2; ++i) {
        apf[i] = *(const float4*)(Ab + (size_t)gr * 2048 + gk + i * 4);
        bpf[i] = *(const float4*)(Bb + (size_t)gr * 2048 + gk + i * 4);
    }
    {
        uint32_t* AhS = gsm32;
        uint32_t* AlS = AhS + GW_TILE;
        uint32_t* BhS = AlS + GW_TILE;
        uint32_t* BlS = BhS + GW_TILE;
#pragma unroll
        for (int i = 0; i < 2; ++i) {
            float4 va = apf[i];
            if (fixA) {
                va.x = nn_fix(va.x); va.y = nn_fix(va.y);
                va.z = nn_fix(va.z); va.w = nn_fix(va.w);
            }
            uint2 hw, lw;
            split4(va, hw, lw);
            *(uint2*)&AhS[wbase + 2 * i] = hw;
            *(uint2*)&AlS[wbase + 2 * i] = lw;
            split4(bpf[i], hw, lw);
            *(uint2*)&BhS[wbase + 2 * i] = hw;
            *(uint2*)&BlS[wbase + 2 * i] = lw;
        }
    }

    for (int ch = 0; ch < 64; ++ch) {
        const int s = ch & 1;
        uint32_t* AhS = gsm32 + (size_t)s * (4 * GW_TILE);
        uint32_t* AlS = AhS + GW_TILE;
        uint32_t* BhS = AlS + GW_TILE;
        uint32_t* BlS = BhS + GW_TILE;
        __syncthreads();

        if (ch < 63) {
            const int k0n = (ch + 1) * 32;
#pragma unroll
            for (int i = 0; i < 2; ++i) {
                apf[i] = *(const float4*)(Ab + (size_t)gr * 2048 + k0n + gk + i * 4);
                bpf[i] = *(const float4*)(Bb + (size_t)gr * 2048 + k0n + gk + i * 4);
            }
        }

#pragma unroll
        for (int ks = 0; ks < 2; ++ks) {
            const int off = ks * 8 + tig;
            uint32_t ah[2][4], al[2][4], bh[4][2], bl[4][2];
#pragma unroll
            for (int mt = 0; mt < 2; ++mt) {
                const int r0 = (warp_m + mt * 16 + g) * GW_LDS + off;
                ah[mt][0] = AhS[r0];
                ah[mt][1] = AhS[r0 + 8 * GW_LDS];
                ah[mt][2] = AhS[r0 + 4];
                ah[mt][3] = AhS[r0 + 8 * GW_LDS + 4];
                al[mt][0] = AlS[r0];
                al[mt][1] = AlS[r0 + 8 * GW_LDS];
                al[mt][2] = AlS[r0 + 4];
                al[mt][3] = AlS[r0 + 8 * GW_LDS + 4];
            }
#pragma unroll
            for (int nt = 0; nt < 4; ++nt) {
                const int n0 = (warp_n + nt * 8 + g) * GW_LDS + off;
                bh[nt][0] = BhS[n0]; bh[nt][1] = BhS[n0 + 4];
                bl[nt][0] = BlS[n0]; bl[nt][1] = BlS[n0 + 4];
            }
#pragma unroll
            for (int mt = 0; mt < 2; ++mt)
#pragma unroll
                for (int nt = 0; nt < 4; ++nt)
                    mma_bf16(c[mt][nt], ah[mt], bh[nt]);
#pragma unroll
            for (int mt = 0; mt < 2; ++mt)
#pragma unroll
                for (int nt = 0; nt < 4; ++nt)
                    mma_bf16(c[mt][nt], ah[mt], bl[nt]);
#pragma unroll
            for (int mt = 0; mt < 2; ++mt)
#pragma unroll
                for (int nt = 0; nt < 4; ++nt)
                    mma_bf16(c[mt][nt], al[mt], bh[nt]);
        }

        if (ch < 63) {
            uint32_t* AhN = gsm32 + (size_t)(s ^ 1) * (4 * GW_TILE);
            uint32_t* AlN = AhN + GW_TILE;
            uint32_t* BhN = AlN + GW_TILE;
            uint32_t* BlN = BhN + GW_TILE;
#pragma unroll
            for (int i = 0; i < 2; ++i) {
                float4 va = apf[i];
                if (fixA) {
                    va.x = nn_fix(va.x); va.y = nn_fix(va.y);
                    va.z = nn_fix(va.z); va.w = nn_fix(va.w);
                }
                uint2 hw, lw;
                split4(va, hw, lw);
                *(uint2*)&AhN[wbase + 2 * i] = hw;
                *(uint2*)&AlN[wbase + 2 * i] = lw;
                split4(bpf[i], hw, lw);
                *(uint2*)&BhN[wbase + 2 * i] = hw;
                *(uint2*)&BlN[wbase + 2 * i] = lw;
            }
        }
    }

#pragma unroll
    for (int mt = 0; mt < 2; ++mt) {
        const int row0 = bm * 128 + warp_m + mt * 16 + g;
#pragma unroll
        for (int nt = 0; nt < 4; ++nt) {
            const int coln = warp_n + nt * 8 + 2 * tig;
            if (mode == 3) {
                float* d0 = Cext + (size_t)row0 * 2048 + bn * 128 + coln;
                float* d1 = Cext + (size_t)(row0 + 8) * 2048 + bn * 128 + coln;
                d0[0] = nn_fix(c[mt][nt][0]); d0[1] = nn_fix(c[mt][nt][1]);
                d1[0] = nn_fix(c[mt][nt][2]); d1[1] = nn_fix(c[mt][nt][3]);
            } else {
                float* Cg = (z == 0) ? g_q : (z == 1) ? g_k : g_v;
                float* base = Cg + (size_t)bn * (TSEQ * HDIM);
                *(float2*)&base[(size_t)row0 * HDIM + coln] =
                    make_float2(c[mt][nt][0], c[mt][nt][1]);
                *(float2*)&base[(size_t)(row0 + 8) * HDIM + coln] =
                    make_float2(c[mt][nt][2], c[mt][nt][3]);
            }
        }
    }
}

// ---------------- RoPE in-place on g_q, g_k ----------------------------------
__global__ void rope_kernel()
{
    const int t = blockIdx.x;
    const int i = threadIdx.x;
    const float pw = (float)pow(10000.0, (double)(2 * i) / 128.0);
    const float inv = 1.0f / pw;
    const float freq = (float)t * inv;
    const float c = cosf(freq);
    const float s = sinf(freq);
#pragma unroll 4
    for (int h = 0; h < NHEAD; ++h) {
        float* q = g_q + ((size_t)(h * TSEQ + t)) * HDIM;
        float x1 = q[i], x2 = q[i + 64];
        q[i]      = __fadd_rn(__fmul_rn(x1, c), __fmul_rn(-x2, s));
        q[i + 64] = __fadd_rn(__fmul_rn(x2, c), __fmul_rn(x1, s));
        float* k = g_k + ((size_t)(h * TSEQ + t)) * HDIM;
        float y1 = k[i], y2 = k[i + 64];
        k[i]      = __fadd_rn(__fmul_rn(y1, c), __fmul_rn(-y2, s));
        k[i + 64] = __fadd_rn(__fmul_rn(y2, c), __fmul_rn(y1, s));
    }
}

// ---------------- threefry-2x32, PARTITIONABLE path --------------------------
__device__ __forceinline__ unsigned rotl32(unsigned x, int d) {
    return (x << d) | (x >> (32 - d));
}

__device__ float jax_uniform42_partitionable(int h)
{
    const unsigned k0 = 0u, k1 = 42u;
    const unsigned k2 = k0 ^ k1 ^ 0x1BD11BDAu;
    const unsigned ks[3] = { k0, k1, k2 };
    unsigned x0 = 0u + k0;
    unsigned x1 = (unsigned)h + k1;
    const int rotA[4] = { 13, 15, 26, 6 };
    const int rotB[4] = { 17, 29, 16, 24 };
#pragma unroll
    for (int i = 0; i < 5; ++i) {
        const int* R = (i & 1) ? rotB : rotA;
#pragma unroll
        for (int j = 0; j < 4; ++j) {
            x0 += x1;
            x1 = rotl32(x1, R[j]);
            x1 ^= x0;
        }
        x0 += ks[(i + 1) % 3];
        x1 += ks[(i + 2) % 3] + (unsigned)(i + 1);
    }
    const unsigned bits = x0 ^ x1;
    return __uint_as_float((bits >> 9) | 0x3f800000u) - 1.0f;
}

// ---------------- last-row stats: p, bern, v_e per head ----------------------
__global__ void __launch_bounds__(256) lastrow_kernel()
{
    const int h = blockIdx.x;
    const int tid = threadIdx.x;
    __shared__ float qv[128];
    __shared__ float s[2048];
    __shared__ float red[256];
    __shared__ float red2[256];
    __shared__ float sh_scale;

    if (tid < 128) qv[tid] = g_q[((size_t)h * TSEQ + 2047) * HDIM + tid];
    __syncthreads();

    for (int k = tid; k < 2048; k += 256) {
        const bool keep = (k < 204) || (k >= 1229);
        float val = -INFINITY;
        if (keep) {
            const float4* kr = (const float4*)(g_k + ((size_t)h * TSEQ + k) * HDIM);
            const float4* q4 = (const float4*)qv;
            float dot = 0.0f;
#pragma unroll
            for (int d4 = 0; d4 < 32; ++d4) {
                float4 a = q4[d4]; float4 b = kr[d4];
                dot = fmaf(a.x, b.x, dot); dot = fmaf(a.y, b.y, dot);
                dot = fmaf(a.z, b.z, dot); dot = fmaf(a.w, b.w, dot);
            }
            val = dot / 11.313708498984760f;
        }
        s[k] = val;
    }
    __syncthreads();

    float lm = -INFINITY;
    for (int k = tid; k < 2048; k += 256) lm = fmaxf(lm, s[k]);
    red[tid] = lm;
    __syncthreads();
    for (int st = 128; st > 0; st >>= 1) {
        if (tid < st) red[tid] = fmaxf(red[tid], red[tid + st]);
        __syncthreads();
    }
    const float m = red[0];
    __syncthreads();

    float ls = 0.0f, lrS = 0.0f;
    for (int k = tid; k < 2048; k += 256) {
        if ((k < 204) || (k >= 1229)) {
            const float e = expf(s[k] - m);
            ls += e;
            if (k >= 1230) lrS += e;
        }
    }
    red[tid] = ls; red2[tid] = lrS;
    __syncthreads();
    for (int st = 128; st > 0; st >>= 1) {
        if (tid < st) { red[tid] += red[tid + st]; red2[tid] += red2[tid + st]; }
        __syncthreads();
    }
    if (tid == 0) {
        const float L = red[0], R = red2[0];
        const float Pev = expf(s[1229] - m) / L;
        const float mean = (R / L) / 818.0f + 1e-6f;
        float p = Pev / mean;
        if (isnan(p)) p = 0.0f;
        p = fminf(fmaxf(p, 0.0f), 1.0f);
        const float u = jax_uniform42_partitionable(h);
        sh_scale = (u < p) ? 1.0f : 0.0f;
    }
    __syncthreads();
    if (tid < 128)
        g_ve[h * HDIM + tid] =
            (g_v[((size_t)h * TSEQ + 1229) * HDIM + tid] * sh_scale) / 819.0f;
}

// ---------------- flash attention, pre-split bf16 hi/lo SMEM -----------------
// grid (32 qtiles, 16 heads), 512 threads (16 warps).
// Warp w: wm=(w>>2)*16 (q rows), wq=w&3: wnS=wq*16 (S cols), wnO=wq*32 (O cols).
// Packed word tiles: Qh/Ql,Kh/Kl [64 rows][68 stride] (d pairs),
// Vth/Vtl [128 d][36 stride] (kcol pairs), Ph/Pl [64 rows][36 stride],
// S fp32 [64][66] for raw scores.
#define AT_QLD 68
#define AT_VLD 36
#define AT_QH 0
#define AT_QL (AT_QH + 64 * AT_QLD)
#define AT_KH (AT_QL + 64 * AT_QLD)
#define AT_KL (AT_KH + 64 * AT_QLD)
#define AT_VTH (AT_KL + 64 * AT_QLD)
#define AT_VTL (AT_VTH + 128 * AT_VLD)
#define AT_PH (AT_VTL + 128 * AT_VLD)
#define AT_PL (AT_PH + 64 * AT_VLD)
#define AT_S  (AT_PL + 64 * AT_VLD)
#define AT_ST (AT_S + 64 * 66)
#define ATTN_SMEM_BYTES ((AT_ST + 256) * 4)

__global__ void __launch_bounds__(512) attn_kernel()
{
    extern __shared__ uint32_t asm32[];
    uint32_t* Qh = asm32 + AT_QH;
    uint32_t* Ql = asm32 + AT_QL;
    uint32_t* Kh = asm32 + AT_KH;
    uint32_t* Kl = asm32 + AT_KL;
    uint32_t* Vth = asm32 + AT_VTH;
    uint32_t* Vtl = asm32 + AT_VTL;
    uint32_t* Ph = asm32 + AT_PH;
    uint32_t* Pl = asm32 + AT_PL;
    float* S = (float*)(asm32 + AT_S);
    float* m_s = (float*)(asm32 + AT_ST);
    float* l_s = m_s + 64;
    float* lr_s = l_s + 64;
    float* fac_s = lr_s + 64;

    const int h   = blockIdx.y;
    const int qt  = blockIdx.x;
    const int tid = threadIdx.x;
    const int wid  = tid >> 5;
    const int lane = tid & 31;
    const int g    = lane >> 2;
    const int tig  = lane & 3;
    const int wm   = (wid >> 2) * 16;
    const int wq   = wid & 3;
    const int wnS  = wq * 16;
    const int wnO  = wq * 32;

    // loader indices: Q/K rows
    const int qr = tid >> 3;        // 0..63
    const int qs = tid & 7;         // 16-float segment
    // V transpose-pack indices
    const int vjp = tid & 31;       // kcol pair 0..31
    const int vds = tid >> 5;       // 0..15 -> 8 d's each

    // ---- load Q once (split to packed hi/lo) ----
    {
        const float* qb = g_q + ((size_t)h * TSEQ + qt * 64 + qr) * HDIM + qs * 16;
#pragma unroll
        for (int i = 0; i < 4; ++i) {
            float4 v = *(const float4*)(qb + i * 4);
            uint2 hw, lw;
            split4(v, hw, lw);
            *(uint2*)&Qh[qr * AT_QLD + qs * 8 + 2 * i] = hw;
            *(uint2*)&Ql[qr * AT_QLD + qs * 8 + 2 * i] = lw;
        }
    }
    if (tid < 64) { m_s[tid] = -INFINITY; l_s[tid] = 0.0f; lr_s[tid] = 0.0f; }

    float oacc[4][4];
#pragma unroll
    for (int i = 0; i < 4; ++i)
#pragma unroll
        for (int j = 0; j < 4; ++j) oacc[i][j] = 0.0f;

    __syncthreads();

    for (int tile = 0; tile < 17; ++tile) {
        const int kb   = (tile < 4) ? tile * 64 : 1229 + (tile - 4) * 64;
        const int kend = (tile < 4) ? 204 : 2048;

        // ---- load K tile (split packed) ----
        {
            const int kc = kb + qr;
            float4 v0 = make_float4(0.f, 0.f, 0.f, 0.f);
            float4 v1 = v0;
            if (kc < kend) {
                const float* kbp = g_k + ((size_t)h * TSEQ + kc) * HDIM + qs * 16;
                v0 = *(const float4*)(kbp);
                v1 = *(const float4*)(kbp + 4);
            }
            uint2 hw, lw;
            split4(v0, hw, lw);
            *(uint2*)&Kh[qr * AT_QLD + qs * 8] = hw;
            *(uint2*)&Kl[qr * AT_QLD + qs * 8] = lw;
            split4(v1, hw, lw);
            *(uint2*)&Kh[qr * AT_QLD + qs * 8 + 2] = hw;
            *(uint2*)&Kl[qr * AT_QLD + qs * 8 + 2] = lw;
            float4 v2 = make_float4(0.f, 0.f, 0.f, 0.f);
            float4 v3 = v2;
            if (kc < kend) {
                const float* kbp = g_k + ((size_t)h * TSEQ + kc) * HDIM + qs * 16;
                v2 = *(const float4*)(kbp + 8);
                v3 = *(const float4*)(kbp + 12);
            }
            split4(v2, hw, lw);
            *(uint2*)&Kh[qr * AT_QLD + qs * 8 + 4] = hw;
            *(uint2*)&Kl[qr * AT_QLD + qs * 8 + 4] = lw;
            split4(v3, hw, lw);
            *(uint2*)&Kh[qr * AT_QLD + qs * 8 + 6] = hw;
            *(uint2*)&Kl[qr * AT_QLD + qs * 8 + 6] = lw;
        }
        // ---- load V tile transpose-packed: Vt[d][kcol pair] ----
        {
            const int kc0 = kb + 2 * vjp;
            const int kc1 = kc0 + 1;
            float4 a0 = make_float4(0.f, 0.f, 0.f, 0.f), a1 = a0, b0 = a0, b1 = a0;
            if (kc0 < kend) {
                const float* vp = g_v + ((size_t)h * TSEQ + kc0) * HDIM + vds * 8;
                a0 = *(const float4*)vp;
                a1 = *(const float4*)(vp + 4);
            }
            if (kc1 < kend) {
                const float* vp = g_v + ((size_t)h * TSEQ + kc1) * HDIM + vds * 8;
                b0 = *(const float4*)vp;
                b1 = *(const float4*)(vp + 4);
            }
            const float r0[8] = { a0.x, a0.y, a0.z, a0.w, a1.x, a1.y, a1.z, a1.w };
            const float r1[8] = { b0.x, b0.y, b0.z, b0.w, b1.x, b1.y, b1.z, b1.w };
#pragma unroll
            for (int i = 0; i < 8; ++i) {
                uint32_t lo;
                const uint32_t hi = split2(r0[i], r1[i], lo);
                Vth[(vds * 8 + i) * AT_VLD + vjp] = hi;
                Vtl[(vds * 8 + i) * AT_VLD + vjp] = lo;
            }
        }
        __syncthreads();

        // ---- S = Q K^T via packed bf16x3 HMMA ----
        float sacc[2][4];
#pragma unroll
        for (int nt = 0; nt < 2; ++nt)
#pragma unroll
            for (int q = 0; q < 4; ++q) sacc[nt][q] = 0.0f;

        const int ar0 = (wm + g) * AT_QLD;
        const int ar1 = (wm + g + 8) * AT_QLD;
#pragma unroll
        for (int ks = 0; ks < 8; ++ks) {
            const int off = ks * 8 + tig;
            uint32_t ah[4], al[4];
            ah[0] = Qh[ar0 + off];     al[0] = Ql[ar0 + off];
            ah[1] = Qh[ar1 + off];     al[1] = Ql[ar1 + off];
            ah[2] = Qh[ar0 + off + 4]; al[2] = Ql[ar0 + off + 4];
            ah[3] = Qh[ar1 + off + 4]; al[3] = Ql[ar1 + off + 4];
            uint32_t bh[2][2], bl[2][2];
#pragma unroll
            for (int nt = 0; nt < 2; ++nt) {
                const int br = (wnS + nt * 8 + g) * AT_QLD + off;
                bh[nt][0] = Kh[br];     bh[nt][1] = Kh[br + 4];
                bl[nt][0] = Kl[br];     bl[nt][1] = Kl[br + 4];
            }
#pragma unroll
            for (int nt = 0; nt < 2; ++nt)
                mma_bf16(sacc[nt], ah, bh[nt]);
#pragma unroll
            for (int nt = 0; nt < 2; ++nt)
                mma_bf16(sacc[nt], ah, bl[nt]);
#pragma unroll
            for (int nt = 0; nt < 2; ++nt)
                mma_bf16(sacc[nt], al, bh[nt]);
        }
#pragma unroll
        for (int nt = 0; nt < 2; ++nt) {
            const int col = wnS + nt * 8 + 2 * tig;
            const int kc = kb + col;
            S[(wm + g) * 66 + col] =
                (kc < kend) ? sacc[nt][0] / 11.313708498984760f : -1e30f;
            S[(wm + g) * 66 + col + 1] =
                (kc + 1 < kend) ? sacc[nt][1] / 11.313708498984760f : -1e30f;
            S[(wm + g + 8) * 66 + col] =
                (kc < kend) ? sacc[nt][2] / 11.313708498984760f : -1e30f;
            S[(wm + g + 8) * 66 + col + 1] =
                (kc + 1 < kend) ? sacc[nt][3] / 11.313708498984760f : -1e30f;
        }
        __syncthreads();

        // ---- softmax: 128 threads, 2 per row; emit packed Ph/Pl ----
        if (tid < 128) {
            const int r = tid >> 1;
            const int hf = tid & 1;
            const float* Sr = S + r * 66 + hf * 32;
            float tm = -1e30f;
#pragma unroll 8
            for (int j = 0; j < 32; ++j) tm = fmaxf(tm, Sr[j]);
            tm = fmaxf(tm, __shfl_xor_sync(0xffffffffu, tm, 1));
            const float mo = m_s[r];
            const float mn = fmaxf(mo, tm);
            const float fac = expf(mo - mn);
            float sum = 0.0f, sumr = 0.0f;
#pragma unroll
            for (int p = 0; p < 16; ++p) {
                const float e0 = expf(Sr[2 * p] - mn);
                const float e1 = expf(Sr[2 * p + 1] - mn);
                sum += e0;
                sum += e1;
                const int col = kb + hf * 32 + 2 * p;
                if (col >= 1230) sumr += e0;
                if (col + 1 >= 1230) sumr += e1;
                uint32_t lo;
                const uint32_t hi = split2(e0, e1, lo);
                Ph[r * AT_VLD + hf * 16 + p] = hi;
                Pl[r * AT_VLD + hf * 16 + p] = lo;
            }
            sum += __shfl_xor_sync(0xffffffffu, sum, 1);
            sumr += __shfl_xor_sync(0xffffffffu, sumr, 1);
            if (hf == 0) {
                l_s[r]  = l_s[r]  * fac + sum;
                lr_s[r] = lr_s[r] * fac + sumr;
                m_s[r]  = mn;
                fac_s[r] = fac;
            }
        }
        __syncthreads();

        // ---- rescale O fragments, then O += P V (packed bf16x3) ----
        {
            const float fA = fac_s[wm + g];
            const float fB = fac_s[wm + g + 8];
#pragma unroll
            for (int nt = 0; nt < 4; ++nt) {
                oacc[nt][0] *= fA; oacc[nt][1] *= fA;
                oacc[nt][2] *= fB; oacc[nt][3] *= fB;
            }
        }
        const int pr0 = (wm + g) * AT_VLD;
        const int pr1 = (wm + g + 8) * AT_VLD;
#pragma unroll
        for (int ks = 0; ks < 4; ++ks) {
            const int off = ks * 8 + tig;
            uint32_t ph[4], pl[4];
            ph[0] = Ph[pr0 + off];     pl[0] = Pl[pr0 + off];
            ph[1] = Ph[pr1 + off];     pl[1] = Pl[pr1 + off];
            ph[2] = Ph[pr0 + off + 4]; pl[2] = Pl[pr0 + off + 4];
            ph[3] = Ph[pr1 + off + 4]; pl[3] = Pl[pr1 + off + 4];
#pragma unroll
            for (int nt = 0; nt < 4; ++nt) {
                const int vb = (wnO + nt * 8 + g) * AT_VLD + off;
                uint32_t vh[2], vl[2];
                vh[0] = Vth[vb];     vh[1] = Vth[vb + 4];
                vl[0] = Vtl[vb];     vl[1] = Vtl[vb + 4];
                mma_bf16(oacc[nt], ph, vh);
                mma_bf16(oacc[nt], ph, vl);
                mma_bf16(oacc[nt], pl, vh);
            }
        }
        __syncthreads();
    }

    // ---- epilogue: normalize + v_e correction ----
    const int qg0 = qt * 64;
    const int rA = wm + g, rB = wm + g + 8;
    const float linvA = 1.0f / l_s[rA];
    const float linvB = 1.0f / l_s[rB];
    const float corrA = (qg0 + rA >= 1792) ? lr_s[rA] * linvA : 0.0f;
    const float corrB = (qg0 + rB >= 1792) ? lr_s[rB] * linvB : 0.0f;
#pragma unroll
    for (int nt = 0; nt < 4; ++nt) {
        const int col = wnO + nt * 8 + 2 * tig;
        const float ve0 = g_ve[h * HDIM + col];
        const float ve1 = g_ve[h * HDIM + col + 1];
        float* dA = g_ctx + (size_t)(qg0 + rA) * 2048 + h * HDIM + col;
        float* dB = g_ctx + (size_t)(qg0 + rB) * 2048 + h * HDIM + col;
        dA[0] = oacc[nt][0] * linvA + corrA * ve0;
        dA[1] = oacc[nt][1] * linvA + corrA * ve1;
        dB[0] = oacc[nt][2] * linvB + corrB * ve0;
        dB[1] = oacc[nt][3] * linvB + corrB * ve1;
    }
}

// ---------------- launch ------------------------------------------------------
extern "C" void kernel_launch(void* const* d_in, const int* in_sizes, int n_in,
                              void* d_out, int out_size)
{
    (void)in_sizes; (void)n_in; (void)out_size;
    const float* hs = (const float*)d_in[0];
    const float* Wq = (const float*)d_in[1];
    const float* Wk = (const float*)d_in[2];
    const float* Wv = (const float*)d_in[3];
    const float* Wo = (const float*)d_in[4];
    float* out = (float*)d_out;

    cudaFuncSetAttribute(gemm_tc_kernel,
                         cudaFuncAttributeMaxDynamicSharedMemorySize,
                         G_SMEM_BYTES);
    cudaFuncSetAttribute(attn_kernel,
                         cudaFuncAttributeMaxDynamicSharedMemorySize,
                         ATTN_SMEM_BYTES);

    gemm_tc_kernel<<<dim3(16, 16, 3), 512, G_SMEM_BYTES>>>(
        hs, Wq, Wk, Wv, nullptr, 0);
    rope_kernel<<<2048, 64>>>();
    lastrow_kernel<<<16, 256>>>();
    attn_kernel<<<dim3(32, 16), 512, ATTN_SMEM_BYTES>>>();
    gemm_tc_kernel<<<dim3(16, 16, 1), 512, G_SMEM_BYTES>>>(
        nullptr, Wo, Wo, Wo, out, 3);
}